// round 2
// baseline (speedup 1.0000x reference)
#include <cuda_runtime.h>
#include <math.h>

// ---------------- problem constants ----------------
#define BB   2
#define TT   2048
#define DD   1024
#define HH   8
#define DH   128
#define KS   512     // slots
#define KRR  16      // top-k
#define CH   128     // chunk
#define NCH  16      // num chunks
#define ETA_C    0.1f
#define FORGET_C 0.01f
#define SCALE_C  0.08838834764831845f   // 1/sqrt(128)

#define BHT (BB*HH*TT)       // 32768 token rows
#define BH  (BB*HH)          // 16

// ---------------- scratch (static device globals; no allocation) --------
__device__ float g_q   [BB*HH*TT*DH];
__device__ float g_k   [BB*HH*TT*DH];
__device__ float g_v   [BB*HH*TT*DH];
__device__ float g_khat[BB*HH*TT*DH];
__device__ float g_reads[BB*HH*TT*DH];
__device__ float g_local[BB*HH*TT*DH];
__device__ float g_hidden[BB*TT*DD];
__device__ float g_slotk[BB*HH*KS*DH];
__device__ float g_slotv[BB*HH*KS*DH];
__device__ float g_rsc[BB*HH*CH*KS];
__device__ float g_wsc[BB*HH*CH*KS];
__device__ int   g_eidx [BB*HH*CH*KRR];
__device__ float g_ewp  [BB*HH*CH*KRR];
__device__ float g_eproj[BB*HH*CH*KRR];

// ---------------- generic SGEMM: C = A * B^T (+bias), K-major both ------
// mode 0: qkv scatter epilogue (N=3072) -> g_q/g_k/g_v [B,H,T,dh]
// mode 1: plain row-major output with bias (final projection)
__global__ __launch_bounds__(256)
void sgemm_kernel(const float* __restrict__ A, const float* __restrict__ Bm,
                  const float* __restrict__ bias, float* __restrict__ Cout,
                  int M, int N, int Kdim, int mode)
{
    __shared__ float As[8][128];
    __shared__ float Bs[8][128];
    int bm = blockIdx.y * 128, bn = blockIdx.x * 128;
    int tid = threadIdx.x;
    int tx = tid & 15, ty = tid >> 4;       // tx -> n dir, ty -> m dir
    int lrow = tid >> 1;
    int lcol = (tid & 1) * 4;
    const float* Aptr = (mode == 1 && A == nullptr) ? g_hidden : A;
    const float* Ag = Aptr + (bm + lrow) * Kdim + lcol;
    const float* Bg = Bm   + (bn + lrow) * Kdim + lcol;
    float acc[8][8];
#pragma unroll
    for (int i = 0; i < 8; i++)
#pragma unroll
        for (int j = 0; j < 8; j++) acc[i][j] = 0.f;

    for (int k0 = 0; k0 < Kdim; k0 += 8) {
        float4 av = *(const float4*)(Ag + k0);
        float4 bv = *(const float4*)(Bg + k0);
        __syncthreads();
        As[lcol+0][lrow] = av.x; As[lcol+1][lrow] = av.y;
        As[lcol+2][lrow] = av.z; As[lcol+3][lrow] = av.w;
        Bs[lcol+0][lrow] = bv.x; Bs[lcol+1][lrow] = bv.y;
        Bs[lcol+2][lrow] = bv.z; Bs[lcol+3][lrow] = bv.w;
        __syncthreads();
#pragma unroll
        for (int kk = 0; kk < 8; kk++) {
            float a[8], b[8];
            *(float4*)(a)   = *(const float4*)&As[kk][ty*8];
            *(float4*)(a+4) = *(const float4*)&As[kk][ty*8+4];
            *(float4*)(b)   = *(const float4*)&Bs[kk][tx*8];
            *(float4*)(b+4) = *(const float4*)&Bs[kk][tx*8+4];
#pragma unroll
            for (int i = 0; i < 8; i++)
#pragma unroll
                for (int j = 0; j < 8; j++) acc[i][j] += a[i]*b[j];
        }
    }

#pragma unroll
    for (int i = 0; i < 8; i++) {
        int row = bm + ty*8 + i;
#pragma unroll
        for (int j = 0; j < 8; j++) {
            int col = bn + tx*8 + j;
            float val = acc[i][j] + bias[col];
            if (mode == 0) {
                int which = col >> 10;
                int h = (col >> 7) & 7;
                int e = col & 127;
                int b = row >> 11;
                int t = row & 2047;
                float* dst = (which == 0) ? g_q : (which == 1) ? g_k : g_v;
                dst[(((b*HH + h)*TT) + t)*DH + e] = val;
            } else {
                Cout[row * N + col] = val;
            }
        }
    }
}

// ---------------- k_hat = l2norm(k) per token --------------------------
__global__ __launch_bounds__(256)
void khat_kernel()
{
    int warp = threadIdx.x >> 5, lane = threadIdx.x & 31;
    int row = blockIdx.x * 8 + warp;
    int base = row * DH;
    float v[4]; float n = 0.f;
#pragma unroll
    for (int i = 0; i < 4; i++) { v[i] = g_k[base + lane + 32*i]; n += v[i]*v[i]; }
#pragma unroll
    for (int off = 16; off; off >>= 1) n += __shfl_xor_sync(0xffffffffu, n, off);
    float inv = 1.0f / (sqrtf(n) + 1e-6f);
#pragma unroll
    for (int i = 0; i < 4; i++) g_khat[base + lane + 32*i] = v[i]*inv;
}

// ---------------- slot init from S_init --------------------------------
__global__ __launch_bounds__(256)
void init_slots_kernel(const float* __restrict__ Sinit)
{
    int warp = threadIdx.x >> 5, lane = threadIdx.x & 31;
    int wid = blockIdx.x * 8 + warp;       // 8192 = BH*KS
    int bh = wid >> 9;
    int s  = wid & 511;
    int h  = bh & 7;
    const float* src = Sinit + s*DD + h*DH;
    float v[4]; float n = 0.f;
#pragma unroll
    for (int i = 0; i < 4; i++) { v[i] = src[lane + 32*i]; n += v[i]*v[i]; }
#pragma unroll
    for (int off = 16; off; off >>= 1) n += __shfl_xor_sync(0xffffffffu, n, off);
    float inv = 1.0f / (sqrtf(n) + 1e-6f);
    float* kd = g_slotk + (bh*KS + s)*DH;
    float* vd = g_slotv + (bh*KS + s)*DH;
#pragma unroll
    for (int i = 0; i < 4; i++) {
        int e = lane + 32*i;
        kd[e] = v[i]*inv;
        vd[e] = v[i];
    }
}

// ---------------- K1: chunk score GEMMs (r & w) -------------------------
// grid: (stile=4, which=2, bh=16), block 256.  C[128x128] = A[128x128] * Slot^T
__global__ __launch_bounds__(256)
void chunk_scores_kernel(int chunk, const float* __restrict__ temp_ptr)
{
    int stile = blockIdx.x, which = blockIdx.y, bh = blockIdx.z;
    const float* A  = ((which == 0) ? g_q : g_khat) + (bh*TT + chunk*CH)*DH;
    const float* Bm = g_slotk + (bh*KS + stile*128)*DH;
    float* out = ((which == 0) ? g_rsc : g_wsc) + bh*CH*KS + stile*128;

    __shared__ float As[8][128];
    __shared__ float Bs[8][128];
    int tid = threadIdx.x;
    int tx = tid & 15, ty = tid >> 4;
    int lrow = tid >> 1;
    int lcol = (tid & 1) * 4;
    const float* Ag = A  + lrow*DH + lcol;
    const float* Bg = Bm + lrow*DH + lcol;
    float acc[8][8];
#pragma unroll
    for (int i = 0; i < 8; i++)
#pragma unroll
        for (int j = 0; j < 8; j++) acc[i][j] = 0.f;

    for (int k0 = 0; k0 < DH; k0 += 8) {
        float4 av = *(const float4*)(Ag + k0);
        float4 bv = *(const float4*)(Bg + k0);
        __syncthreads();
        As[lcol+0][lrow] = av.x; As[lcol+1][lrow] = av.y;
        As[lcol+2][lrow] = av.z; As[lcol+3][lrow] = av.w;
        Bs[lcol+0][lrow] = bv.x; Bs[lcol+1][lrow] = bv.y;
        Bs[lcol+2][lrow] = bv.z; Bs[lcol+3][lrow] = bv.w;
        __syncthreads();
#pragma unroll
        for (int kk = 0; kk < 8; kk++) {
            float a[8], b[8];
            *(float4*)(a)   = *(const float4*)&As[kk][ty*8];
            *(float4*)(a+4) = *(const float4*)&As[kk][ty*8+4];
            *(float4*)(b)   = *(const float4*)&Bs[kk][tx*8];
            *(float4*)(b+4) = *(const float4*)&Bs[kk][tx*8+4];
#pragma unroll
            for (int i = 0; i < 8; i++)
#pragma unroll
                for (int j = 0; j < 8; j++) acc[i][j] += a[i]*b[j];
        }
    }
    float factor = 1.0f;
    if (which == 0) factor = SCALE_C / temp_ptr[0];
#pragma unroll
    for (int i = 0; i < 8; i++)
#pragma unroll
        for (int j = 0; j < 8; j++)
            out[(ty*8 + i)*KS + tx*8 + j] = acc[i][j]*factor;
}

// ---------------- warp-local exact top-16 + softmax ---------------------
__device__ __forceinline__
void topk16_softmax(const float* __restrict__ row, float* p_out, int* i_out)
{
    int lane = threadIdx.x & 31;
    float v[16];
#pragma unroll
    for (int i = 0; i < 16; i++) v[i] = row[lane*16 + i];
    float ev[16];
    float m = 0.f, sum = 0.f;
#pragma unroll
    for (int it = 0; it < 16; it++) {
        float bv = -INFINITY; int bi = 0x7fffffff;
#pragma unroll
        for (int i = 0; i < 16; i++) {
            if (v[i] > bv) { bv = v[i]; bi = lane*16 + i; }
        }
#pragma unroll
        for (int off = 16; off; off >>= 1) {
            float ov = __shfl_xor_sync(0xffffffffu, bv, off);
            int   oi = __shfl_xor_sync(0xffffffffu, bi, off);
            if (ov > bv || (ov == bv && oi < bi)) { bv = ov; bi = oi; }
        }
        if (it == 0) m = bv;
        ev[it] = __expf(bv - m);
        sum += ev[it];
        if (lane == 0) i_out[it] = bi;
#pragma unroll
        for (int i = 0; i < 16; i++)
            if (lane*16 + i == bi) v[i] = -INFINITY;
    }
    if (lane == 0) {
        float inv = 1.0f / sum;
#pragma unroll
        for (int it = 0; it < 16; it++) p_out[it] = ev[it]*inv;
    }
}

// ---------------- K2: per-row topk/read/write-entry kernel --------------
// grid (c=128, bh=16), block 128
__global__ __launch_bounds__(128)
void chunk_rows_kernel(int chunk)
{
    int c = blockIdx.x, bh = blockIdx.y;
    int tid = threadIdx.x;
    int warp = tid >> 5, lane = tid & 31;

    __shared__ float p_r[16]; __shared__ int i_r[16];
    __shared__ float p_w[16]; __shared__ int i_w[16];
    __shared__ float vrow[128];
    __shared__ float sks[16][128];
    __shared__ float proj_sh[16];

    int tbase = (bh*TT + chunk*CH + c)*DH;
    vrow[tid] = g_v[tbase + tid];

    const float* rrow = g_rsc + (bh*CH + c)*KS;
    const float* wrow = g_wsc + (bh*CH + c)*KS;
    if (warp == 0) topk16_softmax(rrow, p_r, i_r);
    if (warp == 1) topk16_softmax(wrow, p_w, i_w);
    __syncthreads();

    // sparse read
    float acc = 0.f;
#pragma unroll
    for (int kr = 0; kr < 16; kr++)
        acc += p_r[kr] * g_slotv[(bh*KS + i_r[kr])*DH + tid];
    g_reads[tbase + tid] = acc;

    // gather selected slot_k rows
#pragma unroll
    for (int kr = 0; kr < 16; kr++)
        sks[kr][tid] = g_slotk[(bh*KS + i_w[kr])*DH + tid];
    __syncthreads();

    // proj[kr] = dot(v_row, sel_k[kr])
#pragma unroll
    for (int j = 0; j < 4; j++) {
        int kr = warp*4 + j;
        float s = 0.f;
#pragma unroll
        for (int i = 0; i < 4; i++) {
            int e = lane + 32*i;
            s += vrow[e] * sks[kr][e];
        }
#pragma unroll
        for (int off = 16; off; off >>= 1) s += __shfl_xor_sync(0xffffffffu, s, off);
        if (lane == 0) proj_sh[kr] = s;
    }
    __syncthreads();

    if (tid < 16) {
        int eb = (bh*CH + c)*KRR + tid;
        g_eidx[eb]  = i_w[tid];
        g_ewp[eb]   = p_w[tid];
        g_eproj[eb] = proj_sh[tid];
    }
}

// ---------------- K3: deterministic slot update -------------------------
// grid (sgroup=8, bh=16), block 256 (8 warps, 8 slots/warp)
__global__ __launch_bounds__(256)
void chunk_update_kernel(int chunk)
{
    int sg = blockIdx.x, bh = blockIdx.y;
    int tid = threadIdx.x;
    int warp = tid >> 5, lane = tid & 31;

    __shared__ int   sidx[CH*KRR];
    __shared__ float swp [CH*KRR];
    __shared__ float sprj[CH*KRR];
    int ebase = bh*CH*KRR;
    for (int j = tid; j < CH*KRR; j += 256) {
        sidx[j] = g_eidx[ebase + j];
        swp[j]  = g_ewp[ebase + j];
        sprj[j] = g_eproj[ebase + j];
    }
    __syncthreads();

    int tokbase = (bh*TT + chunk*CH)*DH;

    for (int sl = warp; sl < 64; sl += 8) {
        int s = sg*64 + sl;
        float accv[4] = {0,0,0,0};
        float acck[4] = {0,0,0,0};
        float swpsum = 0.f, swpp = 0.f;
        for (int b0 = 0; b0 < CH*KRR; b0 += 32) {
            int j = b0 + lane;
            bool mt = (sidx[j] == s);
            unsigned bal = __ballot_sync(0xffffffffu, mt);
            while (bal) {
                int jj = b0 + (__ffs(bal) - 1);
                bal &= bal - 1;
                float wp = swp[jj];
                float pj = sprj[jj];
                int cc = jj >> 4;
                const float* vr = g_v    + tokbase + cc*DH;
                const float* kr = g_khat + tokbase + cc*DH;
#pragma unroll
                for (int i = 0; i < 4; i++) {
                    int e = lane + 32*i;
                    accv[i] += wp * vr[e];
                    acck[i] += wp * kr[e];
                }
                swpsum += wp;
                swpp   += wp * pj;
            }
        }
        float* kd = g_slotk + (bh*KS + s)*DH;
        float* vd = g_slotv + (bh*KS + s)*DH;
        float nk[4]; float nsum = 0.f;
#pragma unroll
        for (int i = 0; i < 4; i++) {
            int e = lane + 32*i;
            float ok = kd[e];
            float nv = (1.0f - FORGET_C) * vd[e] + ETA_C * (accv[i] - swpp * ok);
            vd[e] = nv;
            nk[i] = ok + ETA_C * (acck[i] - swpsum * ok);
            nsum += nk[i]*nk[i];
        }
#pragma unroll
        for (int off = 16; off; off >>= 1) nsum += __shfl_xor_sync(0xffffffffu, nsum, off);
        float inv = 1.0f / (sqrtf(nsum) + 1e-6f);
#pragma unroll
        for (int i = 0; i < 4; i++) kd[lane + 32*i] = nk[i]*inv;
    }
}

// ---------------- local sliding-window attention ------------------------
// grid (qblocks=32, bh=16), block 256. 64 queries/block, 4 lanes/query.
__global__ __launch_bounds__(256)
void local_attn_kernel()
{
    int qb = blockIdx.x, bh = blockIdx.y;
    int qbase = qb * 64;
    int tid = threadIdx.x, warp = tid >> 5, lane = tid & 31;
    int qq = lane >> 2, seg = lane & 3;
    int qpos = qbase + warp*8 + qq;

    __shared__ __align__(16) float Ks[32][128];
    __shared__ __align__(16) float Vs[32][128];

    const float* qptr = g_q + (bh*TT + qpos)*DH;
    float4 qv[8];
#pragma unroll
    for (int i = 0; i < 8; i++)
        qv[i] = *(const float4*)(qptr + seg*4 + 16*i);

    float m = -INFINITY, l = 0.f;
    float4 av[8];
#pragma unroll
    for (int i = 0; i < 8; i++) av[i] = make_float4(0.f,0.f,0.f,0.f);

    int klo = qbase - 511; if (klo < 0) klo = 0;
    int khi = qbase + 63;
    int nk = khi - klo + 1;

    for (int t0 = 0; t0 < nk; t0 += 32) {
        __syncthreads();
        for (int idx = tid; idx < 32*32; idx += 256) {
            int key = idx >> 5, e4 = idx & 31;
            int kp = klo + t0 + key;
            float4 kvv = make_float4(0.f,0.f,0.f,0.f);
            float4 vvv = kvv;
            if (kp <= khi) {
                kvv = *(const float4*)(g_k + (bh*TT + kp)*DH + e4*4);
                vvv = *(const float4*)(g_v + (bh*TT + kp)*DH + e4*4);
            }
            *(float4*)&Ks[key][e4*4] = kvv;
            *(float4*)&Vs[key][e4*4] = vvv;
        }
        __syncthreads();
#pragma unroll 4
        for (int key = 0; key < 32; key++) {
            int kp = klo + t0 + key;
            if (kp > khi) break;
            float s = 0.f;
#pragma unroll
            for (int i = 0; i < 8; i++) {
                float4 kv = *(const float4*)&Ks[key][seg*4 + 16*i];
                s += qv[i].x*kv.x + qv[i].y*kv.y + qv[i].z*kv.z + qv[i].w*kv.w;
            }
            s += __shfl_xor_sync(0xffffffffu, s, 1);
            s += __shfl_xor_sync(0xffffffffu, s, 2);
            if (kp <= qpos && kp >= qpos - 511) {
                s *= SCALE_C;
                if (s > m) {
                    float corr = __expf(m - s);
                    l = l*corr + 1.f;
#pragma unroll
                    for (int i = 0; i < 8; i++) {
                        float4 vv = *(const float4*)&Vs[key][seg*4 + 16*i];
                        av[i].x = av[i].x*corr + vv.x;
                        av[i].y = av[i].y*corr + vv.y;
                        av[i].z = av[i].z*corr + vv.z;
                        av[i].w = av[i].w*corr + vv.w;
                    }
                    m = s;
                } else {
                    float pp = __expf(s - m);
                    l += pp;
#pragma unroll
                    for (int i = 0; i < 8; i++) {
                        float4 vv = *(const float4*)&Vs[key][seg*4 + 16*i];
                        av[i].x += pp*vv.x;
                        av[i].y += pp*vv.y;
                        av[i].z += pp*vv.z;
                        av[i].w += pp*vv.w;
                    }
                }
            }
        }
    }
    float invl = 1.0f / l;
    float* op = g_local + (bh*TT + qpos)*DH;
#pragma unroll
    for (int i = 0; i < 8; i++) {
        float4 o;
        o.x = av[i].x*invl; o.y = av[i].y*invl;
        o.z = av[i].z*invl; o.w = av[i].w*invl;
        *(float4*)(op + seg*4 + 16*i) = o;
    }
}

// ---------------- combine reads + local into hidden ---------------------
__global__ __launch_bounds__(256)
void combine_kernel()
{
    int idx = blockIdx.x * 256 + threadIdx.x;     // over B*H*T*DH
    int e = idx & 127;
    int t = (idx >> 7) & 2047;
    int bhv = idx >> 18;
    int h = bhv & 7;
    int b = bhv >> 3;
    float val = g_reads[idx] + g_local[idx];
    g_hidden[(b*TT + t)*DD + h*DH + e] = val;
}

// ---------------- launch --------------------------------------------------
extern "C" void kernel_launch(void* const* d_in, const int* in_sizes, int n_in,
                              void* d_out, int out_size)
{
    const float* x     = (const float*)d_in[0];
    const float* Wqkv  = (const float*)d_in[1];
    const float* bqkv  = (const float*)d_in[2];
    const float* Wo    = (const float*)d_in[3];
    const float* bo    = (const float*)d_in[4];
    const float* Sinit = (const float*)d_in[5];
    const float* temp  = (const float*)d_in[6];
    float* out = (float*)d_out;

    init_slots_kernel<<<BH*KS/8, 256>>>(Sinit);

    // QKV projection + scatter to heads
    {
        dim3 grid(3072/128, (BB*TT)/128);
        sgemm_kernel<<<grid, 256>>>(x, Wqkv, bqkv, nullptr, BB*TT, 3072, DD, 0);
    }
    khat_kernel<<<BHT/8, 256>>>();

    // sequential chunk scan
    for (int ch = 0; ch < NCH; ch++) {
        chunk_scores_kernel<<<dim3(4, 2, BH), 256>>>(ch, temp);
        chunk_rows_kernel<<<dim3(CH, BH), 128>>>(ch);
        chunk_update_kernel<<<dim3(8, BH), 256>>>(ch);
    }

    // local sliding-window attention
    local_attn_kernel<<<dim3(TT/64, BH), 256>>>();

    // combine heads, output projection
    combine_kernel<<<(BB*HH*TT*DH)/256, 256>>>();
    {
        dim3 grid(DD/128, (BB*TT)/128);
        sgemm_kernel<<<grid, 256>>>(nullptr, Wo, bo, out, BB*TT, DD, DD, 1);
    }
    (void)in_sizes; (void)n_in; (void)out_size;
}

// round 3
// speedup vs baseline: 1.1013x; 1.1013x over previous
#include <cuda_runtime.h>
#include <math.h>

// ---------------- problem constants ----------------
#define BB   2
#define TT   2048
#define DD   1024
#define HH   8
#define DH   128
#define KS   512     // slots
#define KRR  16      // top-k
#define CH   128     // chunk
#define NCH  16      // num chunks
#define ETA_C    0.1f
#define FORGET_C 0.01f
#define SCALE_C  0.08838834764831845f   // 1/sqrt(128)

#define BHT (BB*HH*TT)       // 32768 token rows
#define BH  (BB*HH)          // 16

// ---------------- scratch (static device globals; no allocation) --------
__device__ float g_q   [BB*HH*TT*DH];
__device__ float g_k   [BB*HH*TT*DH];
__device__ float g_v   [BB*HH*TT*DH];
__device__ float g_khat[BB*HH*TT*DH];
__device__ float g_reads[BB*HH*TT*DH];
__device__ float g_local[BB*HH*TT*DH];
__device__ float g_slotk[BB*HH*KS*DH];
__device__ float g_slotv[BB*HH*KS*DH];
__device__ int   g_eidx [BB*HH*CH*KRR];
__device__ float g_ewp  [BB*HH*CH*KRR];
__device__ float g_eproj[BB*HH*CH*KRR];

// fused A-load for the final projection: A = reads + local, head-interleaved
__device__ __forceinline__ float4 fused_load(int row, int col)
{
    int b = row >> 11, t = row & 2047;
    int h = col >> 7,  e = col & 127;
    int idx = (((b*HH + h)*TT) + t)*DH + e;
    float4 r = *(const float4*)&g_reads[idx];
    float4 l = *(const float4*)&g_local[idx];
    return make_float4(r.x+l.x, r.y+l.y, r.z+l.z, r.w+l.w);
}

// ---------------- SGEMM: C = A * B^T (+bias), register-prefetch pipeline
// mode 0: A = explicit ptr, epilogue scatters qkv -> g_q/g_k/g_v
// mode 1: A = g_reads+g_local (fused), epilogue writes Cout row-major
__global__ __launch_bounds__(256)
void sgemm_kernel(const float* __restrict__ A, const float* __restrict__ Bm,
                  const float* __restrict__ bias, float* __restrict__ Cout,
                  int Kdim, int mode, int Ncols)
{
    __shared__ float As[8][128];
    __shared__ float Bs[8][128];
    int bm = blockIdx.y * 128, bn = blockIdx.x * 128;
    int tid = threadIdx.x;
    int tx = tid & 15, ty = tid >> 4;
    int lrow = tid >> 1;
    int lcol = (tid & 1) * 4;
    int arow = bm + lrow;
    const float* Bg = Bm + (bn + lrow) * Kdim + lcol;

    float acc[8][8];
#pragma unroll
    for (int i = 0; i < 8; i++)
#pragma unroll
        for (int j = 0; j < 8; j++) acc[i][j] = 0.f;

    float4 av = mode ? fused_load(arow, lcol)
                     : *(const float4*)(A + arow*Kdim + lcol);
    float4 bv = *(const float4*)(Bg);

    for (int k0 = 0; k0 < Kdim; k0 += 8) {
        __syncthreads();
        As[lcol+0][lrow] = av.x; As[lcol+1][lrow] = av.y;
        As[lcol+2][lrow] = av.z; As[lcol+3][lrow] = av.w;
        Bs[lcol+0][lrow] = bv.x; Bs[lcol+1][lrow] = bv.y;
        Bs[lcol+2][lrow] = bv.z; Bs[lcol+3][lrow] = bv.w;
        __syncthreads();
        if (k0 + 8 < Kdim) {
            av = mode ? fused_load(arow, k0 + 8 + lcol)
                      : *(const float4*)(A + arow*Kdim + k0 + 8 + lcol);
            bv = *(const float4*)(Bg + k0 + 8);
        }
#pragma unroll
        for (int kk = 0; kk < 8; kk++) {
            float a[8], b[8];
            *(float4*)(a)   = *(const float4*)&As[kk][ty*8];
            *(float4*)(a+4) = *(const float4*)&As[kk][ty*8+4];
            *(float4*)(b)   = *(const float4*)&Bs[kk][tx*8];
            *(float4*)(b+4) = *(const float4*)&Bs[kk][tx*8+4];
#pragma unroll
            for (int i = 0; i < 8; i++)
#pragma unroll
                for (int j = 0; j < 8; j++) acc[i][j] += a[i]*b[j];
        }
    }

#pragma unroll
    for (int i = 0; i < 8; i++) {
        int row = bm + ty*8 + i;
#pragma unroll
        for (int j = 0; j < 8; j++) {
            int col = bn + tx*8 + j;
            float val = acc[i][j] + bias[col];
            if (mode == 0) {
                int which = col >> 10;
                int h = (col >> 7) & 7;
                int e = col & 127;
                int b = row >> 11;
                int t = row & 2047;
                float* dst = (which == 0) ? g_q : (which == 1) ? g_k : g_v;
                dst[(((b*HH + h)*TT) + t)*DH + e] = val;
            } else {
                Cout[row * Ncols + col] = val;
            }
        }
    }
}

// ---------------- k_hat = l2norm(k) per token --------------------------
__global__ __launch_bounds__(256)
void khat_kernel()
{
    int warp = threadIdx.x >> 5, lane = threadIdx.x & 31;
    int row = blockIdx.x * 8 + warp;
    int base = row * DH;
    float v[4]; float n = 0.f;
#pragma unroll
    for (int i = 0; i < 4; i++) { v[i] = g_k[base + lane + 32*i]; n += v[i]*v[i]; }
#pragma unroll
    for (int off = 16; off; off >>= 1) n += __shfl_xor_sync(0xffffffffu, n, off);
    float inv = 1.0f / (sqrtf(n) + 1e-6f);
#pragma unroll
    for (int i = 0; i < 4; i++) g_khat[base + lane + 32*i] = v[i]*inv;
}

// ---------------- slot init from S_init --------------------------------
__global__ __launch_bounds__(256)
void init_slots_kernel(const float* __restrict__ Sinit)
{
    int warp = threadIdx.x >> 5, lane = threadIdx.x & 31;
    int wid = blockIdx.x * 8 + warp;       // 8192 = BH*KS
    int bh = wid >> 9;
    int s  = wid & 511;
    int h  = bh & 7;
    const float* src = Sinit + s*DD + h*DH;
    float v[4]; float n = 0.f;
#pragma unroll
    for (int i = 0; i < 4; i++) { v[i] = src[lane + 32*i]; n += v[i]*v[i]; }
#pragma unroll
    for (int off = 16; off; off >>= 1) n += __shfl_xor_sync(0xffffffffu, n, off);
    float inv = 1.0f / (sqrtf(n) + 1e-6f);
    float* kd = g_slotk + (bh*KS + s)*DH;
    float* vd = g_slotv + (bh*KS + s)*DH;
#pragma unroll
    for (int i = 0; i < 4; i++) {
        int e = lane + 32*i;
        kd[e] = v[i]*inv;
        vd[e] = v[i];
    }
}

// ---------------- warp top-16 + softmax from 16 regs/lane ----------------
// score mapping: v[i] (lane) holds slot  (i>>1)*64 + (i&1)*32 + lane
__device__ __forceinline__
void topk16_reg(float* v, float* p_out, int* i_out, int lane)
{
    float ev[16]; float m = 0.f, sum = 0.f;
#pragma unroll
    for (int it = 0; it < 16; it++) {
        float bv = -INFINITY; int bl = 0;
#pragma unroll
        for (int i = 0; i < 16; i++)
            if (v[i] > bv) { bv = v[i]; bl = i; }
        int bi = ((bl >> 1) << 6) + ((bl & 1) << 5) + lane;
#pragma unroll
        for (int off = 16; off; off >>= 1) {
            float ov = __shfl_xor_sync(0xffffffffu, bv, off);
            int   oi = __shfl_xor_sync(0xffffffffu, bi, off);
            if (ov > bv || (ov == bv && oi < bi)) { bv = ov; bi = oi; }
        }
        if (it == 0) m = bv;
        ev[it] = __expf(bv - m);
        sum += ev[it];
        if (lane == 0) i_out[it] = bi;
        int wl = bi & 31;
#pragma unroll
        for (int i = 0; i < 16; i++)
            if (lane == wl && i == bl) v[i] = -INFINITY;
    }
    if (lane == 0) {
        float inv = 1.0f / sum;
#pragma unroll
        for (int it = 0; it < 16; it++) p_out[it] = ev[it]*inv;
    }
}

// ---------------- fused chunk kernel: scores + topk + read/proj ---------
// grid (32, BH): x<16 -> read tasks (8 queries), x>=16 -> write tasks
__global__ __launch_bounds__(256)
void chunk_qk_kernel(int chunk, const float* __restrict__ temp_ptr)
{
    int bh = blockIdx.y;
    int isread = blockIdx.x < 16;
    int q0 = (blockIdx.x & 15) * 8;
    int tid = threadIdx.x, warp = tid >> 5, lane = tid & 31;

    __shared__ float qs[8][128];
    __shared__ float st[64][132];
    __shared__ float pp[8][16];
    __shared__ int   ii[8][16];
    __shared__ float prj[8][16];

    const float* src = (isread ? g_q : g_khat) + (bh*TT + chunk*CH + q0)*DH;
    for (int i = tid; i < 8*128; i += 256)
        qs[i >> 7][i & 127] = src[(i >> 7)*DH + (i & 127)];
    float factor = isread ? (SCALE_C / temp_ptr[0]) : 1.0f;

    float vreg[16];
    const float* skbase = g_slotk + bh*KS*DH;

#pragma unroll 1
    for (int t = 0; t < 8; t++) {
        __syncthreads();
        for (int i = tid; i < 64*32; i += 256) {
            int s = i >> 5, d4 = (i & 31)*4;
            *(float4*)&st[s][d4] = *(const float4*)&skbase[(t*64 + s)*DH + d4];
        }
        __syncthreads();
        float acc0 = 0.f, acc1 = 0.f;
#pragma unroll
        for (int d = 0; d < 128; d += 4) {
            float4 qv = *(const float4*)&qs[warp][d];
            float4 a  = *(const float4*)&st[lane][d];
            float4 b  = *(const float4*)&st[lane + 32][d];
            acc0 += qv.x*a.x + qv.y*a.y + qv.z*a.z + qv.w*a.w;
            acc1 += qv.x*b.x + qv.y*b.y + qv.z*b.z + qv.w*b.w;
        }
        vreg[2*t]   = acc0 * factor;
        vreg[2*t+1] = acc1 * factor;
    }

    topk16_reg(vreg, pp[warp], ii[warp], lane);
    __syncwarp();

    int row = chunk*CH + q0 + warp;
    int tbase = (bh*TT + row)*DH;

    if (isread) {
        float4 acc = make_float4(0.f, 0.f, 0.f, 0.f);
#pragma unroll
        for (int k = 0; k < 16; k++) {
            int s = ii[warp][k];
            float p = pp[warp][k];
            float4 vv = *(const float4*)&g_slotv[(bh*KS + s)*DH + lane*4];
            acc.x += p*vv.x; acc.y += p*vv.y; acc.z += p*vv.z; acc.w += p*vv.w;
        }
        *(float4*)&g_reads[tbase + lane*4] = acc;
    } else {
        float4 vv = *(const float4*)&g_v[tbase + lane*4];
#pragma unroll
        for (int k = 0; k < 16; k++) {
            int s = ii[warp][k];
            float4 kk = *(const float4*)&g_slotk[(bh*KS + s)*DH + lane*4];
            float d = vv.x*kk.x + vv.y*kk.y + vv.z*kk.z + vv.w*kk.w;
#pragma unroll
            for (int off = 16; off; off >>= 1)
                d += __shfl_xor_sync(0xffffffffu, d, off);
            if (lane == 0) prj[warp][k] = d;
        }
        __syncwarp();
        if (lane < 16) {
            int eb = (bh*CH + q0 + warp)*KRR + lane;
            g_eidx[eb]  = ii[warp][lane];
            g_ewp[eb]   = pp[warp][lane];
            g_eproj[eb] = prj[warp][lane];
        }
    }
}

// ---------------- deterministic slot update: warp per slot ---------------
// grid (64, BH), block 256 (8 warps -> 8 slots)
__global__ __launch_bounds__(256)
void chunk_update_kernel(int chunk)
{
    int bh = blockIdx.y;
    int tid = threadIdx.x;
    int warp = tid >> 5, lane = tid & 31;
    int s = blockIdx.x * 8 + warp;

    __shared__ int   sidx[CH*KRR];
    __shared__ float swp [CH*KRR];
    __shared__ float sprj[CH*KRR];
    int ebase = bh*CH*KRR;
    for (int j = tid; j < CH*KRR; j += 256) {
        sidx[j] = g_eidx[ebase + j];
        swp[j]  = g_ewp[ebase + j];
        sprj[j] = g_eproj[ebase + j];
    }
    __syncthreads();

    int tokbase = (bh*TT + chunk*CH)*DH;

    float accv[4] = {0,0,0,0};
    float acck[4] = {0,0,0,0};
    float swpsum = 0.f, swpp = 0.f;
    for (int b0 = 0; b0 < CH*KRR; b0 += 32) {
        bool mt = (sidx[b0 + lane] == s);
        unsigned bal = __ballot_sync(0xffffffffu, mt);
        while (bal) {
            int jj = b0 + (__ffs(bal) - 1);
            bal &= bal - 1;
            float wp = swp[jj];
            float pj = sprj[jj];
            int cc = jj >> 4;
            const float* vr = g_v    + tokbase + cc*DH;
            const float* kr = g_khat + tokbase + cc*DH;
#pragma unroll
            for (int i = 0; i < 4; i++) {
                int e = lane + 32*i;
                accv[i] += wp * vr[e];
                acck[i] += wp * kr[e];
            }
            swpsum += wp;
            swpp   += wp * pj;
        }
    }
    float* kd = g_slotk + (bh*KS + s)*DH;
    float* vd = g_slotv + (bh*KS + s)*DH;
    float nk[4]; float nsum = 0.f;
#pragma unroll
    for (int i = 0; i < 4; i++) {
        int e = lane + 32*i;
        float ok = kd[e];
        float nv = (1.0f - FORGET_C) * vd[e] + ETA_C * (accv[i] - swpp * ok);
        vd[e] = nv;
        nk[i] = ok + ETA_C * (acck[i] - swpsum * ok);
        nsum += nk[i]*nk[i];
    }
#pragma unroll
    for (int off = 16; off; off >>= 1) nsum += __shfl_xor_sync(0xffffffffu, nsum, off);
    float inv = 1.0f / (sqrtf(nsum) + 1e-6f);
#pragma unroll
    for (int i = 0; i < 4; i++) kd[lane + 32*i] = nk[i]*inv;
}

// ---------------- local sliding-window attention ------------------------
// grid (16, BH), block 256: 128 queries/block, 2 queries per 4-lane group
__global__ __launch_bounds__(256)
void local_attn_kernel()
{
    int qb = blockIdx.x, bh = blockIdx.y;
    int qbase = qb * 128;
    int tid = threadIdx.x, warp = tid >> 5, lane = tid & 31;
    int qq = lane >> 2, seg = lane & 3;
    int qA = qbase + warp*16 + qq;
    int qB = qA + 8;

    __shared__ __align__(16) float Ks[32][128];
    __shared__ __align__(16) float Vs[32][128];

    const float* qpA = g_q + (bh*TT + qA)*DH;
    const float* qpB = g_q + (bh*TT + qB)*DH;
    float4 qvA[8], qvB[8];
#pragma unroll
    for (int i = 0; i < 8; i++) {
        qvA[i] = *(const float4*)(qpA + seg*4 + 16*i);
        qvB[i] = *(const float4*)(qpB + seg*4 + 16*i);
    }

    float mA = -INFINITY, lA = 0.f, mB = -INFINITY, lB = 0.f;
    float4 avA[8], avB[8];
#pragma unroll
    for (int i = 0; i < 8; i++) {
        avA[i] = make_float4(0.f,0.f,0.f,0.f);
        avB[i] = make_float4(0.f,0.f,0.f,0.f);
    }

    int klo = qbase - 511; if (klo < 0) klo = 0;
    int khi = qbase + 127;
    int nk = khi - klo + 1;

    for (int t0 = 0; t0 < nk; t0 += 32) {
        __syncthreads();
        for (int idx = tid; idx < 32*32; idx += 256) {
            int key = idx >> 5, e4 = idx & 31;
            int kp = klo + t0 + key;
            float4 kvv = make_float4(0.f,0.f,0.f,0.f);
            float4 vvv = kvv;
            if (kp <= khi) {
                kvv = *(const float4*)(g_k + (bh*TT + kp)*DH + e4*4);
                vvv = *(const float4*)(g_v + (bh*TT + kp)*DH + e4*4);
            }
            *(float4*)&Ks[key][e4*4] = kvv;
            *(float4*)&Vs[key][e4*4] = vvv;
        }
        __syncthreads();
#pragma unroll 2
        for (int key = 0; key < 32; key++) {
            int kp = klo + t0 + key;
            if (kp > khi) break;
            float sA = 0.f, sB = 0.f;
#pragma unroll
            for (int i = 0; i < 8; i++) {
                float4 kv = *(const float4*)&Ks[key][seg*4 + 16*i];
                sA += qvA[i].x*kv.x + qvA[i].y*kv.y + qvA[i].z*kv.z + qvA[i].w*kv.w;
                sB += qvB[i].x*kv.x + qvB[i].y*kv.y + qvB[i].z*kv.z + qvB[i].w*kv.w;
            }
            sA += __shfl_xor_sync(0xffffffffu, sA, 1);
            sA += __shfl_xor_sync(0xffffffffu, sA, 2);
            sB += __shfl_xor_sync(0xffffffffu, sB, 1);
            sB += __shfl_xor_sync(0xffffffffu, sB, 2);
            bool okA = (kp <= qA) && (kp >= qA - 511);
            bool okB = (kp <= qB) && (kp >= qB - 511);
            float pA = 0.f, cA = 1.f, pB = 0.f, cB = 1.f;
            if (okA) {
                float sc = sA * SCALE_C;
                float nm = fmaxf(mA, sc);
                cA = __expf(mA - nm);
                pA = __expf(sc - nm);
                mA = nm;
                lA = lA*cA + pA;
            }
            if (okB) {
                float sc = sB * SCALE_C;
                float nm = fmaxf(mB, sc);
                cB = __expf(mB - nm);
                pB = __expf(sc - nm);
                mB = nm;
                lB = lB*cB + pB;
            }
            if (okA | okB) {
#pragma unroll
                for (int i = 0; i < 8; i++) {
                    float4 vv = *(const float4*)&Vs[key][seg*4 + 16*i];
                    if (okA) {
                        avA[i].x = avA[i].x*cA + pA*vv.x;
                        avA[i].y = avA[i].y*cA + pA*vv.y;
                        avA[i].z = avA[i].z*cA + pA*vv.z;
                        avA[i].w = avA[i].w*cA + pA*vv.w;
                    }
                    if (okB) {
                        avB[i].x = avB[i].x*cB + pB*vv.x;
                        avB[i].y = avB[i].y*cB + pB*vv.y;
                        avB[i].z = avB[i].z*cB + pB*vv.z;
                        avB[i].w = avB[i].w*cB + pB*vv.w;
                    }
                }
            }
        }
    }
    float ivA = 1.0f / lA, ivB = 1.0f / lB;
    float* opA = g_local + (bh*TT + qA)*DH;
    float* opB = g_local + (bh*TT + qB)*DH;
#pragma unroll
    for (int i = 0; i < 8; i++) {
        float4 oA, oB;
        oA.x = avA[i].x*ivA; oA.y = avA[i].y*ivA; oA.z = avA[i].z*ivA; oA.w = avA[i].w*ivA;
        oB.x = avB[i].x*ivB; oB.y = avB[i].y*ivB; oB.z = avB[i].z*ivB; oB.w = avB[i].w*ivB;
        *(float4*)(opA + seg*4 + 16*i) = oA;
        *(float4*)(opB + seg*4 + 16*i) = oB;
    }
}

// ---------------- launch --------------------------------------------------
extern "C" void kernel_launch(void* const* d_in, const int* in_sizes, int n_in,
                              void* d_out, int out_size)
{
    const float* x     = (const float*)d_in[0];
    const float* Wqkv  = (const float*)d_in[1];
    const float* bqkv  = (const float*)d_in[2];
    const float* Wo    = (const float*)d_in[3];
    const float* bo    = (const float*)d_in[4];
    const float* Sinit = (const float*)d_in[5];
    const float* temp  = (const float*)d_in[6];
    float* out = (float*)d_out;

    init_slots_kernel<<<BH*KS/8, 256>>>(Sinit);

    // QKV projection + scatter to heads
    sgemm_kernel<<<dim3(3072/128, (BB*TT)/128), 256>>>(x, Wqkv, bqkv, nullptr, DD, 0, 3072);
    khat_kernel<<<BHT/8, 256>>>();

    // sequential chunk scan (2 launches per chunk)
    for (int ch = 0; ch < NCH; ch++) {
        chunk_qk_kernel<<<dim3(32, BH), 256>>>(ch, temp);
        chunk_update_kernel<<<dim3(64, BH), 256>>>(ch);
    }

    // local sliding-window attention
    local_attn_kernel<<<dim3(TT/128, BH), 256>>>();

    // output projection with fused combine (A = reads + local)
    sgemm_kernel<<<dim3(DD/128, (BB*TT)/128), 256>>>(nullptr, Wo, bo, out, DD, 1, DD);

    (void)in_sizes; (void)n_in; (void)out_size;
}

// round 4
// speedup vs baseline: 1.4000x; 1.2712x over previous
#include <cuda_runtime.h>
#include <cuda_bf16.h>
#include <math.h>

// ---------------- problem constants ----------------
#define BB   2
#define TT   2048
#define DD   1024
#define HH   8
#define DH   128
#define KS   512
#define KRR  16
#define CH   128
#define NCH  16
#define ETA_C    0.1f
#define FORGET_C 0.01f
#define SCALE_C  0.08838834764831845f

#define BHT (BB*HH*TT)
#define BH  (BB*HH)

// ---------------- scratch ----------------
__device__ float g_q   [BB*HH*TT*DH];
__device__ float g_k   [BB*HH*TT*DH];
__device__ float g_v   [BB*HH*TT*DH];
__device__ float g_khat[BB*HH*TT*DH];
__device__ float g_reads[BB*HH*TT*DH];
__device__ float g_local[BB*HH*TT*DH];
__device__ float g_slotk[BB*HH*KS*DH];
__device__ float g_slotv[BB*HH*KS*DH];
__device__ int   g_eidx [BB*HH*CH*KRR];
__device__ float g_ewp  [BB*HH*CH*KRR];
__device__ float g_eproj[BB*HH*CH*KRR];

// fused A-load for final projection: A = reads + local, head-interleaved
__device__ __forceinline__ float4 fused_load(int row, int col)
{
    int b = row >> 11, t = row & 2047;
    int h = col >> 7,  e = col & 127;
    int idx = (((b*HH + h)*TT) + t)*DH + e;
    float4 r = *(const float4*)&g_reads[idx];
    float4 l = *(const float4*)&g_local[idx];
    return make_float4(r.x+l.x, r.y+l.y, r.z+l.z, r.w+l.w);
}

// ---------------- bf16-split MMA GEMM ----------------
__device__ __forceinline__ void mma16816(float* d, const unsigned* a, const unsigned* b)
{
    asm volatile(
        "mma.sync.aligned.m16n8k16.row.col.f32.bf16.bf16.f32 "
        "{%0,%1,%2,%3}, {%4,%5,%6,%7}, {%8,%9}, {%0,%1,%2,%3};\n"
        : "+f"(d[0]), "+f"(d[1]), "+f"(d[2]), "+f"(d[3])
        : "r"(a[0]), "r"(a[1]), "r"(a[2]), "r"(a[3]), "r"(b[0]), "r"(b[1]));
}

__device__ __forceinline__ void split_store(float4 v, __nv_bfloat16* Hp, __nv_bfloat16* Lp)
{
    float f[4] = {v.x, v.y, v.z, v.w};
#pragma unroll
    for (int p = 0; p < 2; p++) {
        __nv_bfloat16 h0 = __float2bfloat16(f[2*p]);
        __nv_bfloat16 h1 = __float2bfloat16(f[2*p+1]);
        __nv_bfloat16 l0 = __float2bfloat16(f[2*p]   - __bfloat162float(h0));
        __nv_bfloat16 l1 = __float2bfloat16(f[2*p+1] - __bfloat162float(h1));
        unsigned hp = (unsigned)__bfloat16_as_ushort(h0) | ((unsigned)__bfloat16_as_ushort(h1) << 16);
        unsigned lp = (unsigned)__bfloat16_as_ushort(l0) | ((unsigned)__bfloat16_as_ushort(l1) << 16);
        *(unsigned*)(Hp + 2*p) = hp;
        *(unsigned*)(Lp + 2*p) = lp;
    }
}

__device__ __forceinline__ void write_c(int mode, float* Cout, int Ncols,
                                        int row, int col, float val)
{
    if (mode == 0) {
        int which = col >> 10;
        int h = (col >> 7) & 7;
        int e = col & 127;
        int b = row >> 11;
        int t = row & 2047;
        float* dst = (which == 0) ? g_q : (which == 1) ? g_k : g_v;
        dst[(((b*HH + h)*TT) + t)*DH + e] = val;
    } else {
        Cout[row * Ncols + col] = val;
    }
}

// C = A * B^T + bias, A fp32 (or fused reads+local when mode==1), B fp32 weights.
// Internally: A,B split into bf16 hi/lo, 3 MMAs per tile. Tile 128x128, K-panels of 16.
__global__ __launch_bounds__(256)
void mma_gemm(const float* __restrict__ A, const float* __restrict__ Bm,
              const float* __restrict__ bias, float* __restrict__ Cout,
              int Kdim, int mode, int Ncols)
{
    __shared__ __nv_bfloat16 Ah[128][24], Al[128][24];
    __shared__ __nv_bfloat16 Bh[128][24], Bl[128][24];

    int bm = blockIdx.y * 128, bn = blockIdx.x * 128;
    int tid = threadIdx.x;
    int warp = tid >> 5, lane = tid & 31;
    int wm = warp >> 2, wn = warp & 3;    // 2 x 4 warp grid, 64x32 per warp
    int lr = lane >> 2, lc = lane & 3;

    int srow = tid >> 1;
    int sk   = (tid & 1) * 8;

    float acc[4][4][4];
#pragma unroll
    for (int i = 0; i < 4; i++)
#pragma unroll
        for (int j = 0; j < 4; j++)
#pragma unroll
            for (int r = 0; r < 4; r++) acc[i][j][r] = 0.f;

    int arow = bm + srow, brow = bn + srow;
    float4 a0v = mode ? fused_load(arow, sk)     : *(const float4*)(A + arow*Kdim + sk);
    float4 a1v = mode ? fused_load(arow, sk + 4) : *(const float4*)(A + arow*Kdim + sk + 4);
    float4 b0v = *(const float4*)(Bm + brow*Kdim + sk);
    float4 b1v = *(const float4*)(Bm + brow*Kdim + sk + 4);

    for (int kp = 0; kp < Kdim; kp += 16) {
        __syncthreads();
        split_store(a0v, &Ah[srow][sk],   &Al[srow][sk]);
        split_store(a1v, &Ah[srow][sk+4], &Al[srow][sk+4]);
        split_store(b0v, &Bh[srow][sk],   &Bl[srow][sk]);
        split_store(b1v, &Bh[srow][sk+4], &Bl[srow][sk+4]);
        __syncthreads();
        if (kp + 16 < Kdim) {
            int kn = kp + 16;
            a0v = mode ? fused_load(arow, kn + sk)     : *(const float4*)(A + arow*Kdim + kn + sk);
            a1v = mode ? fused_load(arow, kn + sk + 4) : *(const float4*)(A + arow*Kdim + kn + sk + 4);
            b0v = *(const float4*)(Bm + brow*Kdim + kn + sk);
            b1v = *(const float4*)(Bm + brow*Kdim + kn + sk + 4);
        }

        unsigned Afh[4][4], Afl[4][4], Bfh[4][2], Bfl[4][2];
#pragma unroll
        for (int mi = 0; mi < 4; mi++) {
            int r = wm*64 + mi*16 + lr;
            Afh[mi][0] = *(const unsigned*)&Ah[r][lc*2];
            Afh[mi][1] = *(const unsigned*)&Ah[r+8][lc*2];
            Afh[mi][2] = *(const unsigned*)&Ah[r][lc*2+8];
            Afh[mi][3] = *(const unsigned*)&Ah[r+8][lc*2+8];
            Afl[mi][0] = *(const unsigned*)&Al[r][lc*2];
            Afl[mi][1] = *(const unsigned*)&Al[r+8][lc*2];
            Afl[mi][2] = *(const unsigned*)&Al[r][lc*2+8];
            Afl[mi][3] = *(const unsigned*)&Al[r+8][lc*2+8];
        }
#pragma unroll
        for (int ni = 0; ni < 4; ni++) {
            int n = wn*32 + ni*8 + lr;
            Bfh[ni][0] = *(const unsigned*)&Bh[n][lc*2];
            Bfh[ni][1] = *(const unsigned*)&Bh[n][lc*2+8];
            Bfl[ni][0] = *(const unsigned*)&Bl[n][lc*2];
            Bfl[ni][1] = *(const unsigned*)&Bl[n][lc*2+8];
        }
#pragma unroll
        for (int mi = 0; mi < 4; mi++)
#pragma unroll
            for (int ni = 0; ni < 4; ni++) {
                mma16816(acc[mi][ni], Afh[mi], Bfh[ni]);
                mma16816(acc[mi][ni], Afh[mi], Bfl[ni]);
                mma16816(acc[mi][ni], Afl[mi], Bfh[ni]);
            }
    }

#pragma unroll
    for (int mi = 0; mi < 4; mi++)
#pragma unroll
        for (int ni = 0; ni < 4; ni++) {
            int row0 = bm + wm*64 + mi*16 + lr;
            int col0 = bn + wn*32 + ni*8 + lc*2;
            write_c(mode, Cout, Ncols, row0,   col0,   acc[mi][ni][0] + bias[col0]);
            write_c(mode, Cout, Ncols, row0,   col0+1, acc[mi][ni][1] + bias[col0+1]);
            write_c(mode, Cout, Ncols, row0+8, col0,   acc[mi][ni][2] + bias[col0]);
            write_c(mode, Cout, Ncols, row0+8, col0+1, acc[mi][ni][3] + bias[col0+1]);
        }
}

// ---------------- k_hat = l2norm(k) ----------------
__global__ __launch_bounds__(256)
void khat_kernel()
{
    int warp = threadIdx.x >> 5, lane = threadIdx.x & 31;
    int row = blockIdx.x * 8 + warp;
    int base = row * DH;
    float v[4]; float n = 0.f;
#pragma unroll
    for (int i = 0; i < 4; i++) { v[i] = g_k[base + lane + 32*i]; n += v[i]*v[i]; }
#pragma unroll
    for (int off = 16; off; off >>= 1) n += __shfl_xor_sync(0xffffffffu, n, off);
    float inv = 1.0f / (sqrtf(n) + 1e-6f);
#pragma unroll
    for (int i = 0; i < 4; i++) g_khat[base + lane + 32*i] = v[i]*inv;
}

// ---------------- slot init ----------------
__global__ __launch_bounds__(256)
void init_slots_kernel(const float* __restrict__ Sinit)
{
    int warp = threadIdx.x >> 5, lane = threadIdx.x & 31;
    int wid = blockIdx.x * 8 + warp;
    int bh = wid >> 9;
    int s  = wid & 511;
    int h  = bh & 7;
    const float* src = Sinit + s*DD + h*DH;
    float v[4]; float n = 0.f;
#pragma unroll
    for (int i = 0; i < 4; i++) { v[i] = src[lane + 32*i]; n += v[i]*v[i]; }
#pragma unroll
    for (int off = 16; off; off >>= 1) n += __shfl_xor_sync(0xffffffffu, n, off);
    float inv = 1.0f / (sqrtf(n) + 1e-6f);
    float* kd = g_slotk + (bh*KS + s)*DH;
    float* vd = g_slotv + (bh*KS + s)*DH;
#pragma unroll
    for (int i = 0; i < 4; i++) {
        int e = lane + 32*i;
        kd[e] = v[i]*inv;
        vd[e] = v[i];
    }
}

// ---------------- top-16 + softmax, results in ALL lanes' regs ----------
// mapping: v[i] on lane holds slot (i>>1)*64 + (i&1)*32 + lane
__device__ __forceinline__
void topk16_all(float* v, int lane, int* oi, float* op)
{
    float m = 0.f, sum = 0.f;
#pragma unroll
    for (int it = 0; it < 16; it++) {
        float bv = -INFINITY; int bl = 0;
#pragma unroll
        for (int i = 0; i < 16; i++)
            if (v[i] > bv) { bv = v[i]; bl = i; }
        int bi = ((bl >> 1) << 6) + ((bl & 1) << 5) + lane;
#pragma unroll
        for (int off = 16; off; off >>= 1) {
            float ov = __shfl_xor_sync(0xffffffffu, bv, off);
            int   o2 = __shfl_xor_sync(0xffffffffu, bi, off);
            if (ov > bv || (ov == bv && o2 < bi)) { bv = ov; bi = o2; }
        }
        if (it == 0) m = bv;
        op[it] = __expf(bv - m);
        sum += op[it];
        oi[it] = bi;
        int wl = bi & 31;
        int wloc = ((bi >> 6) << 1) | ((bi >> 5) & 1);
#pragma unroll
        for (int i = 0; i < 16; i++)
            if (lane == wl && i == wloc) v[i] = -INFINITY;
    }
    float inv = 1.0f / sum;
#pragma unroll
    for (int it = 0; it < 16; it++) op[it] *= inv;
}

// ---------------- fused chunk kernel: scores + topk + read/proj ---------
// grid (8, 2, 16): 16 queries/block, warp owns 2 queries x all 512 slots
__global__ __launch_bounds__(256)
void chunk_qk_kernel(int chunk, const float* __restrict__ temp_ptr)
{
    int bh = blockIdx.z;
    int isread = (blockIdx.y == 0);
    int q0 = blockIdx.x * 16;
    int tid = threadIdx.x, warp = tid >> 5, lane = tid & 31;

    __shared__ float qs[16][128];
    __shared__ float st[64][132];

    const float* src = (isread ? g_q : g_khat) + (bh*TT + chunk*CH + q0)*DH;
    for (int i = tid; i < 16*128; i += 256)
        qs[i >> 7][i & 127] = src[(i >> 7)*DH + (i & 127)];
    float factor = isread ? (SCALE_C / temp_ptr[0]) : 1.0f;

    float vreg[2][16];
    const float* skbase = g_slotk + bh*KS*DH;

#pragma unroll 1
    for (int t = 0; t < 8; t++) {
        __syncthreads();
        for (int i = tid; i < 64*32; i += 256) {
            int s = i >> 5, d4 = (i & 31)*4;
            *(float4*)&st[s][d4] = *(const float4*)&skbase[(t*64 + s)*DH + d4];
        }
        __syncthreads();
        float a00 = 0.f, a01 = 0.f, a10 = 0.f, a11 = 0.f;
#pragma unroll
        for (int d = 0; d < 128; d += 4) {
            float4 a = *(const float4*)&st[lane][d];
            float4 b = *(const float4*)&st[lane + 32][d];
            float4 q0v = *(const float4*)&qs[warp*2][d];
            float4 q1v = *(const float4*)&qs[warp*2 + 1][d];
            a00 += q0v.x*a.x + q0v.y*a.y + q0v.z*a.z + q0v.w*a.w;
            a01 += q0v.x*b.x + q0v.y*b.y + q0v.z*b.z + q0v.w*b.w;
            a10 += q1v.x*a.x + q1v.y*a.y + q1v.z*a.z + q1v.w*a.w;
            a11 += q1v.x*b.x + q1v.y*b.y + q1v.z*b.z + q1v.w*b.w;
        }
        vreg[0][2*t]   = a00 * factor;
        vreg[0][2*t+1] = a01 * factor;
        vreg[1][2*t]   = a10 * factor;
        vreg[1][2*t+1] = a11 * factor;
    }

#pragma unroll
    for (int j = 0; j < 2; j++) {
        int oi[16]; float op[16];
        topk16_all(vreg[j], lane, oi, op);

        int row = chunk*CH + q0 + warp*2 + j;
        int tbase = (bh*TT + row)*DH;

        if (isread) {
            float4 acc = make_float4(0.f, 0.f, 0.f, 0.f);
#pragma unroll
            for (int k = 0; k < 16; k++) {
                float4 vv = *(const float4*)&g_slotv[(bh*KS + oi[k])*DH + lane*4];
                acc.x += op[k]*vv.x; acc.y += op[k]*vv.y;
                acc.z += op[k]*vv.z; acc.w += op[k]*vv.w;
            }
            *(float4*)&g_reads[tbase + lane*4] = acc;
        } else {
            float4 vv = *(const float4*)&g_v[tbase + lane*4];
            int eb = (bh*CH + q0 + warp*2 + j)*KRR;
#pragma unroll
            for (int k = 0; k < 16; k++) {
                float4 kk = *(const float4*)&g_slotk[(bh*KS + oi[k])*DH + lane*4];
                float d = vv.x*kk.x + vv.y*kk.y + vv.z*kk.z + vv.w*kk.w;
#pragma unroll
                for (int off = 16; off; off >>= 1)
                    d += __shfl_xor_sync(0xffffffffu, d, off);
                if (lane == 0) {
                    g_eidx[eb + k]  = oi[k];
                    g_ewp[eb + k]   = op[k];
                    g_eproj[eb + k] = d;
                }
            }
        }
    }
}

// ---------------- deterministic slot update ----------------
__global__ __launch_bounds__(256)
void chunk_update_kernel(int chunk)
{
    int bh = blockIdx.y;
    int tid = threadIdx.x;
    int warp = tid >> 5, lane = tid & 31;
    int s = blockIdx.x * 8 + warp;

    __shared__ int   sidx[CH*KRR];
    __shared__ float swp [CH*KRR];
    __shared__ float sprj[CH*KRR];
    int ebase = bh*CH*KRR;
    for (int j = tid; j < CH*KRR; j += 256) {
        sidx[j] = g_eidx[ebase + j];
        swp[j]  = g_ewp[ebase + j];
        sprj[j] = g_eproj[ebase + j];
    }
    __syncthreads();

    int tokbase = (bh*TT + chunk*CH)*DH;

    float accv[4] = {0,0,0,0};
    float acck[4] = {0,0,0,0};
    float swpsum = 0.f, swpp = 0.f;
    for (int b0 = 0; b0 < CH*KRR; b0 += 32) {
        bool mt = (sidx[b0 + lane] == s);
        unsigned bal = __ballot_sync(0xffffffffu, mt);
        while (bal) {
            int jj = b0 + (__ffs(bal) - 1);
            bal &= bal - 1;
            float wp = swp[jj];
            float pj = sprj[jj];
            int cc = jj >> 4;
            const float* vr = g_v    + tokbase + cc*DH;
            const float* kr = g_khat + tokbase + cc*DH;
#pragma unroll
            for (int i = 0; i < 4; i++) {
                int e = lane + 32*i;
                accv[i] += wp * vr[e];
                acck[i] += wp * kr[e];
            }
            swpsum += wp;
            swpp   += wp * pj;
        }
    }
    float* kd = g_slotk + (bh*KS + s)*DH;
    float* vd = g_slotv + (bh*KS + s)*DH;
    float nk[4]; float nsum = 0.f;
#pragma unroll
    for (int i = 0; i < 4; i++) {
        int e = lane + 32*i;
        float ok = kd[e];
        float nv = (1.0f - FORGET_C) * vd[e] + ETA_C * (accv[i] - swpp * ok);
        vd[e] = nv;
        nk[i] = ok + ETA_C * (acck[i] - swpsum * ok);
        nsum += nk[i]*nk[i];
    }
#pragma unroll
    for (int off = 16; off; off >>= 1) nsum += __shfl_xor_sync(0xffffffffu, nsum, off);
    float inv = 1.0f / (sqrtf(nsum) + 1e-6f);
#pragma unroll
    for (int i = 0; i < 4; i++) kd[lane + 32*i] = nk[i]*inv;
}

// ---------------- local sliding-window attention ----------------
__global__ __launch_bounds__(256)
void local_attn_kernel()
{
    int qb = blockIdx.x, bh = blockIdx.y;
    int qbase = qb * 128;
    int tid = threadIdx.x, warp = tid >> 5, lane = tid & 31;
    int qq = lane >> 2, seg = lane & 3;
    int qA = qbase + warp*16 + qq;
    int qB = qA + 8;

    __shared__ __align__(16) float Ks[32][128];
    __shared__ __align__(16) float Vs[32][128];

    const float* qpA = g_q + (bh*TT + qA)*DH;
    const float* qpB = g_q + (bh*TT + qB)*DH;
    float4 qvA[8], qvB[8];
#pragma unroll
    for (int i = 0; i < 8; i++) {
        qvA[i] = *(const float4*)(qpA + seg*4 + 16*i);
        qvB[i] = *(const float4*)(qpB + seg*4 + 16*i);
    }

    float mA = -INFINITY, lA = 0.f, mB = -INFINITY, lB = 0.f;
    float4 avA[8], avB[8];
#pragma unroll
    for (int i = 0; i < 8; i++) {
        avA[i] = make_float4(0.f,0.f,0.f,0.f);
        avB[i] = make_float4(0.f,0.f,0.f,0.f);
    }

    int klo = qbase - 511; if (klo < 0) klo = 0;
    int khi = qbase + 127;
    int nk = khi - klo + 1;

    for (int t0 = 0; t0 < nk; t0 += 32) {
        __syncthreads();
        for (int idx = tid; idx < 32*32; idx += 256) {
            int key = idx >> 5, e4 = idx & 31;
            int kp = klo + t0 + key;
            float4 kvv = make_float4(0.f,0.f,0.f,0.f);
            float4 vvv = kvv;
            if (kp <= khi) {
                kvv = *(const float4*)(g_k + (bh*TT + kp)*DH + e4*4);
                vvv = *(const float4*)(g_v + (bh*TT + kp)*DH + e4*4);
            }
            *(float4*)&Ks[key][e4*4] = kvv;
            *(float4*)&Vs[key][e4*4] = vvv;
        }
        __syncthreads();
#pragma unroll 2
        for (int key = 0; key < 32; key++) {
            int kp = klo + t0 + key;
            if (kp > khi) break;
            float sA = 0.f, sB = 0.f;
#pragma unroll
            for (int i = 0; i < 8; i++) {
                float4 kv = *(const float4*)&Ks[key][seg*4 + 16*i];
                sA += qvA[i].x*kv.x + qvA[i].y*kv.y + qvA[i].z*kv.z + qvA[i].w*kv.w;
                sB += qvB[i].x*kv.x + qvB[i].y*kv.y + qvB[i].z*kv.z + qvB[i].w*kv.w;
            }
            sA += __shfl_xor_sync(0xffffffffu, sA, 1);
            sA += __shfl_xor_sync(0xffffffffu, sA, 2);
            sB += __shfl_xor_sync(0xffffffffu, sB, 1);
            sB += __shfl_xor_sync(0xffffffffu, sB, 2);
            bool okA = (kp <= qA) && (kp >= qA - 511);
            bool okB = (kp <= qB) && (kp >= qB - 511);
            float pA = 0.f, cA = 1.f, pB = 0.f, cB = 1.f;
            if (okA) {
                float sc = sA * SCALE_C;
                float nm = fmaxf(mA, sc);
                cA = __expf(mA - nm);
                pA = __expf(sc - nm);
                mA = nm;
                lA = lA*cA + pA;
            }
            if (okB) {
                float sc = sB * SCALE_C;
                float nm = fmaxf(mB, sc);
                cB = __expf(mB - nm);
                pB = __expf(sc - nm);
                mB = nm;
                lB = lB*cB + pB;
            }
            if (okA | okB) {
#pragma unroll
                for (int i = 0; i < 8; i++) {
                    float4 vv = *(const float4*)&Vs[key][seg*4 + 16*i];
                    if (okA) {
                        avA[i].x = avA[i].x*cA + pA*vv.x;
                        avA[i].y = avA[i].y*cA + pA*vv.y;
                        avA[i].z = avA[i].z*cA + pA*vv.z;
                        avA[i].w = avA[i].w*cA + pA*vv.w;
                    }
                    if (okB) {
                        avB[i].x = avB[i].x*cB + pB*vv.x;
                        avB[i].y = avB[i].y*cB + pB*vv.y;
                        avB[i].z = avB[i].z*cB + pB*vv.z;
                        avB[i].w = avB[i].w*cB + pB*vv.w;
                    }
                }
            }
        }
    }
    float ivA = 1.0f / lA, ivB = 1.0f / lB;
    float* opA = g_local + (bh*TT + qA)*DH;
    float* opB = g_local + (bh*TT + qB)*DH;
#pragma unroll
    for (int i = 0; i < 8; i++) {
        float4 oA, oB;
        oA.x = avA[i].x*ivA; oA.y = avA[i].y*ivA; oA.z = avA[i].z*ivA; oA.w = avA[i].w*ivA;
        oB.x = avB[i].x*ivB; oB.y = avB[i].y*ivB; oB.z = avB[i].z*ivB; oB.w = avB[i].w*ivB;
        *(float4*)(opA + seg*4 + 16*i) = oA;
        *(float4*)(opB + seg*4 + 16*i) = oB;
    }
}

// ---------------- launch ----------------
extern "C" void kernel_launch(void* const* d_in, const int* in_sizes, int n_in,
                              void* d_out, int out_size)
{
    const float* x     = (const float*)d_in[0];
    const float* Wqkv  = (const float*)d_in[1];
    const float* bqkv  = (const float*)d_in[2];
    const float* Wo    = (const float*)d_in[3];
    const float* bo    = (const float*)d_in[4];
    const float* Sinit = (const float*)d_in[5];
    const float* temp  = (const float*)d_in[6];
    float* out = (float*)d_out;

    init_slots_kernel<<<BH*KS/8, 256>>>(Sinit);

    // QKV projection (bf16-split tensor cores) + scatter to heads
    mma_gemm<<<dim3(3072/128, (BB*TT)/128), 256>>>(x, Wqkv, bqkv, nullptr, DD, 0, 3072);
    khat_kernel<<<BHT/8, 256>>>();

    // sequential chunk scan
    for (int ch = 0; ch < NCH; ch++) {
        chunk_qk_kernel<<<dim3(8, 2, BH), 256>>>(ch, temp);
        chunk_update_kernel<<<dim3(64, BH), 256>>>(ch);
    }

    // local sliding-window attention
    local_attn_kernel<<<dim3(TT/128, BH), 256>>>();

    // output projection (bf16-split tensor cores, fused reads+local)
    mma_gemm<<<dim3(DD/128, (BB*TT)/128), 256>>>(nullptr, Wo, bo, out, DD, 1, DD);

    (void)in_sizes; (void)n_in; (void)out_size;
}

// round 6
// speedup vs baseline: 1.5538x; 1.1098x over previous
#include <cuda_runtime.h>
#include <cuda_bf16.h>
#include <math.h>

// ---------------- problem constants ----------------
#define BB   2
#define TT   2048
#define DD   1024
#define HH   8
#define DH   128
#define KS   512
#define KRR  16
#define CH   128
#define NCH  16
#define ETA_C    0.1f
#define FORGET_C 0.01f
#define SCALE_C  0.08838834764831845f

#define BHT (BB*HH*TT)
#define BH  (BB*HH)

// ---------------- scratch ----------------
__device__ float g_q   [BB*HH*TT*DH];
__device__ float g_k   [BB*HH*TT*DH];
__device__ float g_v   [BB*HH*TT*DH];
__device__ float g_khat[BB*HH*TT*DH];
__device__ float g_reads[BB*HH*TT*DH];
__device__ float g_local[BB*HH*TT*DH];
__device__ float g_slotk[BB*HH*KS*DH];
__device__ float g_slotv[BB*HH*KS*DH];
__device__ __nv_bfloat16 g_skh[BB*HH*KS*DH];   // slot_k bf16 hi
__device__ __nv_bfloat16 g_skl[BB*HH*KS*DH];   // slot_k bf16 lo
__device__ int   g_eidx [BB*HH*CH*KRR];
__device__ float g_ewp  [BB*HH*CH*KRR];
__device__ float g_eproj[BB*HH*CH*KRR];

// fused A-load for final projection: A = reads + local, head-interleaved
__device__ __forceinline__ float4 fused_load(int row, int col)
{
    int b = row >> 11, t = row & 2047;
    int h = col >> 7,  e = col & 127;
    int idx = (((b*HH + h)*TT) + t)*DH + e;
    float4 r = *(const float4*)&g_reads[idx];
    float4 l = *(const float4*)&g_local[idx];
    return make_float4(r.x+l.x, r.y+l.y, r.z+l.z, r.w+l.w);
}

// ---------------- bf16-split MMA primitives ----------------
__device__ __forceinline__ void mma16816(float* d, const unsigned* a, const unsigned* b)
{
    asm volatile(
        "mma.sync.aligned.m16n8k16.row.col.f32.bf16.bf16.f32 "
        "{%0,%1,%2,%3}, {%4,%5,%6,%7}, {%8,%9}, {%0,%1,%2,%3};\n"
        : "+f"(d[0]), "+f"(d[1]), "+f"(d[2]), "+f"(d[3])
        : "r"(a[0]), "r"(a[1]), "r"(a[2]), "r"(a[3]), "r"(b[0]), "r"(b[1]));
}

__device__ __forceinline__ void split_store(float4 v, __nv_bfloat16* Hp, __nv_bfloat16* Lp)
{
    float f[4] = {v.x, v.y, v.z, v.w};
#pragma unroll
    for (int p = 0; p < 2; p++) {
        __nv_bfloat16 h0 = __float2bfloat16(f[2*p]);
        __nv_bfloat16 h1 = __float2bfloat16(f[2*p+1]);
        __nv_bfloat16 l0 = __float2bfloat16(f[2*p]   - __bfloat162float(h0));
        __nv_bfloat16 l1 = __float2bfloat16(f[2*p+1] - __bfloat162float(h1));
        unsigned hp = (unsigned)__bfloat16_as_ushort(h0) | ((unsigned)__bfloat16_as_ushort(h1) << 16);
        unsigned lp = (unsigned)__bfloat16_as_ushort(l0) | ((unsigned)__bfloat16_as_ushort(l1) << 16);
        *(unsigned*)(Hp + 2*p) = hp;
        *(unsigned*)(Lp + 2*p) = lp;
    }
}

__device__ __forceinline__ void write_c(int mode, float* Cout, int Ncols,
                                        int row, int col, float val)
{
    if (mode == 0) {
        int which = col >> 10;
        int h = (col >> 7) & 7;
        int e = col & 127;
        int b = row >> 11;
        int t = row & 2047;
        float* dst = (which == 0) ? g_q : (which == 1) ? g_k : g_v;
        dst[(((b*HH + h)*TT) + t)*DH + e] = val;
    } else {
        Cout[row * Ncols + col] = val;
    }
}

// ---------------- big GEMMs (qkv / out-proj), bf16-split ----------------
__global__ __launch_bounds__(256)
void mma_gemm(const float* __restrict__ A, const float* __restrict__ Bm,
              const float* __restrict__ bias, float* __restrict__ Cout,
              int Kdim, int mode, int Ncols)
{
    __shared__ __nv_bfloat16 Ah[128][24], Al[128][24];
    __shared__ __nv_bfloat16 Bh[128][24], Bl[128][24];

    int bm = blockIdx.y * 128, bn = blockIdx.x * 128;
    int tid = threadIdx.x;
    int warp = tid >> 5, lane = tid & 31;
    int wm = warp >> 2, wn = warp & 3;
    int lr = lane >> 2, lc = lane & 3;

    int srow = tid >> 1;
    int sk   = (tid & 1) * 8;

    float acc[4][4][4];
#pragma unroll
    for (int i = 0; i < 4; i++)
#pragma unroll
        for (int j = 0; j < 4; j++)
#pragma unroll
            for (int r = 0; r < 4; r++) acc[i][j][r] = 0.f;

    int arow = bm + srow, brow = bn + srow;
    float4 a0v = mode ? fused_load(arow, sk)     : *(const float4*)(A + arow*Kdim + sk);
    float4 a1v = mode ? fused_load(arow, sk + 4) : *(const float4*)(A + arow*Kdim + sk + 4);
    float4 b0v = *(const float4*)(Bm + brow*Kdim + sk);
    float4 b1v = *(const float4*)(Bm + brow*Kdim + sk + 4);

    for (int kp = 0; kp < Kdim; kp += 16) {
        __syncthreads();
        split_store(a0v, &Ah[srow][sk],   &Al[srow][sk]);
        split_store(a1v, &Ah[srow][sk+4], &Al[srow][sk+4]);
        split_store(b0v, &Bh[srow][sk],   &Bl[srow][sk]);
        split_store(b1v, &Bh[srow][sk+4], &Bl[srow][sk+4]);
        __syncthreads();
        if (kp + 16 < Kdim) {
            int kn = kp + 16;
            a0v = mode ? fused_load(arow, kn + sk)     : *(const float4*)(A + arow*Kdim + kn + sk);
            a1v = mode ? fused_load(arow, kn + sk + 4) : *(const float4*)(A + arow*Kdim + kn + sk + 4);
            b0v = *(const float4*)(Bm + brow*Kdim + kn + sk);
            b1v = *(const float4*)(Bm + brow*Kdim + kn + sk + 4);
        }

        unsigned Afh[4][4], Afl[4][4], Bfh[4][2], Bfl[4][2];
#pragma unroll
        for (int mi = 0; mi < 4; mi++) {
            int r = wm*64 + mi*16 + lr;
            Afh[mi][0] = *(const unsigned*)&Ah[r][lc*2];
            Afh[mi][1] = *(const unsigned*)&Ah[r+8][lc*2];
            Afh[mi][2] = *(const unsigned*)&Ah[r][lc*2+8];
            Afh[mi][3] = *(const unsigned*)&Ah[r+8][lc*2+8];
            Afl[mi][0] = *(const unsigned*)&Al[r][lc*2];
            Afl[mi][1] = *(const unsigned*)&Al[r+8][lc*2];
            Afl[mi][2] = *(const unsigned*)&Al[r][lc*2+8];
            Afl[mi][3] = *(const unsigned*)&Al[r+8][lc*2+8];
        }
#pragma unroll
        for (int ni = 0; ni < 4; ni++) {
            int n = wn*32 + ni*8 + lr;
            Bfh[ni][0] = *(const unsigned*)&Bh[n][lc*2];
            Bfh[ni][1] = *(const unsigned*)&Bh[n][lc*2+8];
            Bfl[ni][0] = *(const unsigned*)&Bl[n][lc*2];
            Bfl[ni][1] = *(const unsigned*)&Bl[n][lc*2+8];
        }
#pragma unroll
        for (int mi = 0; mi < 4; mi++)
#pragma unroll
            for (int ni = 0; ni < 4; ni++) {
                mma16816(acc[mi][ni], Afh[mi], Bfh[ni]);
                mma16816(acc[mi][ni], Afh[mi], Bfl[ni]);
                mma16816(acc[mi][ni], Afl[mi], Bfh[ni]);
            }
    }

#pragma unroll
    for (int mi = 0; mi < 4; mi++)
#pragma unroll
        for (int ni = 0; ni < 4; ni++) {
            int row0 = bm + wm*64 + mi*16 + lr;
            int col0 = bn + wn*32 + ni*8 + lc*2;
            write_c(mode, Cout, Ncols, row0,   col0,   acc[mi][ni][0] + bias[col0]);
            write_c(mode, Cout, Ncols, row0,   col0+1, acc[mi][ni][1] + bias[col0+1]);
            write_c(mode, Cout, Ncols, row0+8, col0,   acc[mi][ni][2] + bias[col0]);
            write_c(mode, Cout, Ncols, row0+8, col0+1, acc[mi][ni][3] + bias[col0+1]);
        }
}

// ---------------- k_hat = l2norm(k) ----------------
__global__ __launch_bounds__(256)
void khat_kernel()
{
    int warp = threadIdx.x >> 5, lane = threadIdx.x & 31;
    int row = blockIdx.x * 8 + warp;
    int base = row * DH;
    float v[4]; float n = 0.f;
#pragma unroll
    for (int i = 0; i < 4; i++) { v[i] = g_k[base + lane + 32*i]; n += v[i]*v[i]; }
#pragma unroll
    for (int off = 16; off; off >>= 1) n += __shfl_xor_sync(0xffffffffu, n, off);
    float inv = 1.0f / (sqrtf(n) + 1e-6f);
#pragma unroll
    for (int i = 0; i < 4; i++) g_khat[base + lane + 32*i] = v[i]*inv;
}

// ---------------- slot init (writes fp32 + bf16 hi/lo) ----------------
__global__ __launch_bounds__(256)
void init_slots_kernel(const float* __restrict__ Sinit)
{
    int warp = threadIdx.x >> 5, lane = threadIdx.x & 31;
    int wid = blockIdx.x * 8 + warp;
    int bh = wid >> 9;
    int s  = wid & 511;
    int h  = bh & 7;
    const float* src = Sinit + s*DD + h*DH;
    float v[4]; float n = 0.f;
#pragma unroll
    for (int i = 0; i < 4; i++) { v[i] = src[lane + 32*i]; n += v[i]*v[i]; }
#pragma unroll
    for (int off = 16; off; off >>= 1) n += __shfl_xor_sync(0xffffffffu, n, off);
    float inv = 1.0f / (sqrtf(n) + 1e-6f);
    int rb = (bh*KS + s)*DH;
#pragma unroll
    for (int i = 0; i < 4; i++) {
        int e = lane + 32*i;
        float kk = v[i]*inv;
        g_slotk[rb + e] = kk;
        g_slotv[rb + e] = v[i];
        __nv_bfloat16 hv = __float2bfloat16(kk);
        g_skh[rb + e] = hv;
        g_skl[rb + e] = __float2bfloat16(kk - __bfloat162float(hv));
    }
}

// ---------------- top-16 + softmax from smem score row ------------------
// v[i] on lane holds slot i*32 + lane
__device__ __forceinline__
void topk16_smem(const float* __restrict__ row, int lane, int* oi, float* op)
{
    float v[16];
#pragma unroll
    for (int i = 0; i < 16; i++) v[i] = row[i*32 + lane];
    float m = 0.f, sum = 0.f;
#pragma unroll
    for (int it = 0; it < 16; it++) {
        float bv = -INFINITY; int bl = 0;
#pragma unroll
        for (int i = 0; i < 16; i++)
            if (v[i] > bv) { bv = v[i]; bl = i; }
        int bi = bl*32 + lane;
#pragma unroll
        for (int off = 16; off; off >>= 1) {
            float ov = __shfl_xor_sync(0xffffffffu, bv, off);
            int   o2 = __shfl_xor_sync(0xffffffffu, bi, off);
            if (ov > bv || (ov == bv && o2 < bi)) { bv = ov; bi = o2; }
        }
        if (it == 0) m = bv;
        op[it] = __expf(bv - m);
        sum += op[it];
        oi[it] = bi;
        int wl = bi & 31;
        int wloc = bi >> 5;
#pragma unroll
        for (int i = 0; i < 16; i++)
            if (lane == wl && i == wloc) v[i] = -INFINITY;
    }
    float inv = 1.0f / sum;
#pragma unroll
    for (int it = 0; it < 16; it++) op[it] *= inv;
}

// ---------------- fused chunk kernel: MMA scores + topk + read/proj ----
// grid (8, BH), block 256, dynamic smem.
// Block computes 32 M-rows (16 q + 16 khat) x 512 slots, K=128, bf16-split MMA.
#define AP 136
#define SP 520
#define CQK_SMEM (32*AP*2*2 + 128*AP*2*2 + 32*SP*4)
__global__ __launch_bounds__(256)
void chunk_qk_kernel(int chunk, const float* __restrict__ temp_ptr)
{
    extern __shared__ char smemraw[];
    __nv_bfloat16* Ah = (__nv_bfloat16*)smemraw;   // [32][AP]
    __nv_bfloat16* Al = Ah + 32*AP;
    __nv_bfloat16* Bh = Al + 32*AP;                // [128][AP]
    __nv_bfloat16* Bl = Bh + 128*AP;
    float* scores = (float*)(Bl + 128*AP);         // [32][SP]

    int qt = blockIdx.x, bh = blockIdx.y;
    int q0 = qt * 16;
    int tid = threadIdx.x;
    int warp = tid >> 5, lane = tid & 31;
    int wm = warp >> 2, wn = warp & 3;
    int lr = lane >> 2, lc = lane & 3;

    float fq = SCALE_C / temp_ptr[0];
    int tokrow0 = bh*TT + chunk*CH + q0;

    // load + split A: rows 0-15 q, rows 16-31 khat
    for (int i = tid; i < 32*32; i += 256) {
        int r = i >> 5, c4 = (i & 31)*4;
        const float* src = (r < 16 ? g_q : g_khat) + (tokrow0 + (r & 15))*DH + c4;
        split_store(*(const float4*)src, &Ah[r*AP + c4], &Al[r*AP + c4]);
    }

    int slotbase = bh*KS;

#pragma unroll 1
    for (int t = 0; t < 4; t++) {
        __syncthreads();
        for (int i = tid; i < 128*16; i += 256) {
            int row = i >> 4, seg = (i & 15)*8;
            int gidx = (slotbase + t*128 + row)*DH + seg;
            *(uint4*)&Bh[row*AP + seg] = *(const uint4*)&g_skh[gidx];
            *(uint4*)&Bl[row*AP + seg] = *(const uint4*)&g_skl[gidx];
        }
        __syncthreads();

        float acc[4][4];
#pragma unroll
        for (int n = 0; n < 4; n++)
#pragma unroll
            for (int r = 0; r < 4; r++) acc[n][r] = 0.f;

#pragma unroll
        for (int kt = 0; kt < 8; kt++) {
            int k0 = kt*16;
            unsigned Afh[4], Afl[4];
            int r = wm*16 + lr;
            Afh[0] = *(const unsigned*)&Ah[r*AP + k0 + lc*2];
            Afh[1] = *(const unsigned*)&Ah[(r+8)*AP + k0 + lc*2];
            Afh[2] = *(const unsigned*)&Ah[r*AP + k0 + lc*2 + 8];
            Afh[3] = *(const unsigned*)&Ah[(r+8)*AP + k0 + lc*2 + 8];
            Afl[0] = *(const unsigned*)&Al[r*AP + k0 + lc*2];
            Afl[1] = *(const unsigned*)&Al[(r+8)*AP + k0 + lc*2];
            Afl[2] = *(const unsigned*)&Al[r*AP + k0 + lc*2 + 8];
            Afl[3] = *(const unsigned*)&Al[(r+8)*AP + k0 + lc*2 + 8];
#pragma unroll
            for (int n = 0; n < 4; n++) {
                int nr = wn*32 + n*8 + lr;
                unsigned Bf0[2], Bf1[2];
                Bf0[0] = *(const unsigned*)&Bh[nr*AP + k0 + lc*2];
                Bf0[1] = *(const unsigned*)&Bh[nr*AP + k0 + lc*2 + 8];
                Bf1[0] = *(const unsigned*)&Bl[nr*AP + k0 + lc*2];
                Bf1[1] = *(const unsigned*)&Bl[nr*AP + k0 + lc*2 + 8];
                mma16816(acc[n], Afh, Bf0);
                mma16816(acc[n], Afh, Bf1);
                mma16816(acc[n], Afl, Bf0);
            }
        }
        float factor = (wm == 0) ? fq : 1.0f;
#pragma unroll
        for (int n = 0; n < 4; n++) {
            int col = t*128 + wn*32 + n*8 + lc*2;
            int row0 = wm*16 + lr;
            scores[row0*SP + col]       = acc[n][0]*factor;
            scores[row0*SP + col + 1]   = acc[n][1]*factor;
            scores[(row0+8)*SP + col]   = acc[n][2]*factor;
            scores[(row0+8)*SP + col+1] = acc[n][3]*factor;
        }
    }
    __syncthreads();

    // topk + read / proj.  warps 0-3: q queries; warps 4-7: khat queries.
    bool isq = warp < 4;
#pragma unroll 1
    for (int j = 0; j < 4; j++) {
        int qi = (warp & 3)*4 + j;
        int srow = isq ? qi : (16 + qi);
        int oi[16]; float op[16];
        topk16_smem(&scores[srow*SP], lane, oi, op);

        int tbase = (tokrow0 + qi)*DH;

        if (isq) {
            float4 acc = make_float4(0.f, 0.f, 0.f, 0.f);
#pragma unroll
            for (int k = 0; k < 16; k++) {
                float4 vv = *(const float4*)&g_slotv[(slotbase + oi[k])*DH + lane*4];
                acc.x += op[k]*vv.x; acc.y += op[k]*vv.y;
                acc.z += op[k]*vv.z; acc.w += op[k]*vv.w;
            }
            *(float4*)&g_reads[tbase + lane*4] = acc;
        } else {
            float4 vv = *(const float4*)&g_v[tbase + lane*4];
            int eb = (bh*CH + q0 + qi)*KRR;
#pragma unroll
            for (int k = 0; k < 16; k++) {
                float4 kk = *(const float4*)&g_slotk[(slotbase + oi[k])*DH + lane*4];
                float d = vv.x*kk.x + vv.y*kk.y + vv.z*kk.z + vv.w*kk.w;
#pragma unroll
                for (int off = 16; off; off >>= 1)
                    d += __shfl_xor_sync(0xffffffffu, d, off);
                if (lane == 0) {
                    g_eidx[eb + k]  = oi[k];
                    g_ewp[eb + k]   = op[k];
                    g_eproj[eb + k] = d;
                }
            }
        }
    }
}

// ---------------- deterministic slot update (writes fp32 + bf16) --------
__global__ __launch_bounds__(256)
void chunk_update_kernel(int chunk)
{
    int bh = blockIdx.y;
    int tid = threadIdx.x;
    int warp = tid >> 5, lane = tid & 31;
    int s = blockIdx.x * 8 + warp;

    __shared__ int   sidx[CH*KRR];
    __shared__ float swp [CH*KRR];
    __shared__ float sprj[CH*KRR];
    int ebase = bh*CH*KRR;
    for (int j = tid; j < CH*KRR; j += 256) {
        sidx[j] = g_eidx[ebase + j];
        swp[j]  = g_ewp[ebase + j];
        sprj[j] = g_eproj[ebase + j];
    }
    __syncthreads();

    int tokbase = (bh*TT + chunk*CH)*DH;

    float accv[4] = {0,0,0,0};
    float acck[4] = {0,0,0,0};
    float swpsum = 0.f, swpp = 0.f;
    for (int b0 = 0; b0 < CH*KRR; b0 += 32) {
        bool mt = (sidx[b0 + lane] == s);
        unsigned bal = __ballot_sync(0xffffffffu, mt);
        while (bal) {
            int jj = b0 + (__ffs(bal) - 1);
            bal &= bal - 1;
            float wp = swp[jj];
            float pj = sprj[jj];
            int cc = jj >> 4;
            const float* vr = g_v    + tokbase + cc*DH;
            const float* kr = g_khat + tokbase + cc*DH;
#pragma unroll
            for (int i = 0; i < 4; i++) {
                int e = lane + 32*i;
                accv[i] += wp * vr[e];
                acck[i] += wp * kr[e];
            }
            swpsum += wp;
            swpp   += wp * pj;
        }
    }
    int rb = (bh*KS + s)*DH;
    float* kd = g_slotk + rb;
    float* vd = g_slotv + rb;
    float nk[4]; float nsum = 0.f;
#pragma unroll
    for (int i = 0; i < 4; i++) {
        int e = lane + 32*i;
        float ok = kd[e];
        float nv = (1.0f - FORGET_C) * vd[e] + ETA_C * (accv[i] - swpp * ok);
        vd[e] = nv;
        nk[i] = ok + ETA_C * (acck[i] - swpsum * ok);
        nsum += nk[i]*nk[i];
    }
#pragma unroll
    for (int off = 16; off; off >>= 1) nsum += __shfl_xor_sync(0xffffffffu, nsum, off);
    float inv = 1.0f / (sqrtf(nsum) + 1e-6f);
#pragma unroll
    for (int i = 0; i < 4; i++) {
        int e = lane + 32*i;
        float val = nk[i]*inv;
        kd[e] = val;
        __nv_bfloat16 hv = __float2bfloat16(val);
        g_skh[rb + e] = hv;
        g_skl[rb + e] = __float2bfloat16(val - __bfloat162float(hv));
    }
}

// ---------------- local sliding-window attention ----------------
__global__ __launch_bounds__(256)
void local_attn_kernel()
{
    int qb = blockIdx.x, bh = blockIdx.y;
    int qbase = qb * 128;
    int tid = threadIdx.x, warp = tid >> 5, lane = tid & 31;
    int qq = lane >> 2, seg = lane & 3;
    int qA = qbase + warp*16 + qq;
    int qB = qA + 8;

    __shared__ __align__(16) float Ks[32][128];
    __shared__ __align__(16) float Vs[32][128];

    const float* qpA = g_q + (bh*TT + qA)*DH;
    const float* qpB = g_q + (bh*TT + qB)*DH;
    float4 qvA[8], qvB[8];
#pragma unroll
    for (int i = 0; i < 8; i++) {
        qvA[i] = *(const float4*)(qpA + seg*4 + 16*i);
        qvB[i] = *(const float4*)(qpB + seg*4 + 16*i);
    }

    float mA = -INFINITY, lA = 0.f, mB = -INFINITY, lB = 0.f;
    float4 avA[8], avB[8];
#pragma unroll
    for (int i = 0; i < 8; i++) {
        avA[i] = make_float4(0.f,0.f,0.f,0.f);
        avB[i] = make_float4(0.f,0.f,0.f,0.f);
    }

    int klo = qbase - 511; if (klo < 0) klo = 0;
    int khi = qbase + 127;
    int nk = khi - klo + 1;

    for (int t0 = 0; t0 < nk; t0 += 32) {
        __syncthreads();
        for (int idx = tid; idx < 32*32; idx += 256) {
            int key = idx >> 5, e4 = idx & 31;
            int kp = klo + t0 + key;
            float4 kvv = make_float4(0.f,0.f,0.f,0.f);
            float4 vvv = kvv;
            if (kp <= khi) {
                kvv = *(const float4*)(g_k + (bh*TT + kp)*DH + e4*4);
                vvv = *(const float4*)(g_v + (bh*TT + kp)*DH + e4*4);
            }
            *(float4*)&Ks[key][e4*4] = kvv;
            *(float4*)&Vs[key][e4*4] = vvv;
        }
        __syncthreads();
#pragma unroll 2
        for (int key = 0; key < 32; key++) {
            int kp = klo + t0 + key;
            if (kp > khi) break;
            float sA = 0.f, sB = 0.f;
#pragma unroll
            for (int i = 0; i < 8; i++) {
                float4 kv = *(const float4*)&Ks[key][seg*4 + 16*i];
                sA += qvA[i].x*kv.x + qvA[i].y*kv.y + qvA[i].z*kv.z + qvA[i].w*kv.w;
                sB += qvB[i].x*kv.x + qvB[i].y*kv.y + qvB[i].z*kv.z + qvB[i].w*kv.w;
            }
            sA += __shfl_xor_sync(0xffffffffu, sA, 1);
            sA += __shfl_xor_sync(0xffffffffu, sA, 2);
            sB += __shfl_xor_sync(0xffffffffu, sB, 1);
            sB += __shfl_xor_sync(0xffffffffu, sB, 2);
            bool okA = (kp <= qA) && (kp >= qA - 511);
            bool okB = (kp <= qB) && (kp >= qB - 511);
            float pA = 0.f, cA = 1.f, pB = 0.f, cB = 1.f;
            if (okA) {
                float sc = sA * SCALE_C;
                float nm = fmaxf(mA, sc);
                cA = __expf(mA - nm);
                pA = __expf(sc - nm);
                mA = nm;
                lA = lA*cA + pA;
            }
            if (okB) {
                float sc = sB * SCALE_C;
                float nm = fmaxf(mB, sc);
                cB = __expf(mB - nm);
                pB = __expf(sc - nm);
                mB = nm;
                lB = lB*cB + pB;
            }
            if (okA | okB) {
#pragma unroll
                for (int i = 0; i < 8; i++) {
                    float4 vv = *(const float4*)&Vs[key][seg*4 + 16*i];
                    if (okA) {
                        avA[i].x = avA[i].x*cA + pA*vv.x;
                        avA[i].y = avA[i].y*cA + pA*vv.y;
                        avA[i].z = avA[i].z*cA + pA*vv.z;
                        avA[i].w = avA[i].w*cA + pA*vv.w;
                    }
                    if (okB) {
                        avB[i].x = avB[i].x*cB + pB*vv.x;
                        avB[i].y = avB[i].y*cB + pB*vv.y;
                        avB[i].z = avB[i].z*cB + pB*vv.z;
                        avB[i].w = avB[i].w*cB + pB*vv.w;
                    }
                }
            }
        }
    }
    float ivA = 1.0f / lA, ivB = 1.0f / lB;
    float* opA = g_local + (bh*TT + qA)*DH;
    float* opB = g_local + (bh*TT + qB)*DH;
#pragma unroll
    for (int i = 0; i < 8; i++) {
        float4 oA, oB;
        oA.x = avA[i].x*ivA; oA.y = avA[i].y*ivA; oA.z = avA[i].z*ivA; oA.w = avA[i].w*ivA;
        oB.x = avB[i].x*ivB; oB.y = avB[i].y*ivB; oB.z = avB[i].z*ivB; oB.w = avB[i].w*ivB;
        *(float4*)(opA + seg*4 + 16*i) = oA;
        *(float4*)(opB + seg*4 + 16*i) = oB;
    }
}

// ---------------- launch ----------------
extern "C" void kernel_launch(void* const* d_in, const int* in_sizes, int n_in,
                              void* d_out, int out_size)
{
    const float* x     = (const float*)d_in[0];
    const float* Wqkv  = (const float*)d_in[1];
    const float* bqkv  = (const float*)d_in[2];
    const float* Wo    = (const float*)d_in[3];
    const float* bo    = (const float*)d_in[4];
    const float* Sinit = (const float*)d_in[5];
    const float* temp  = (const float*)d_in[6];
    float* out = (float*)d_out;

    cudaFuncSetAttribute(chunk_qk_kernel,
                         cudaFuncAttributeMaxDynamicSharedMemorySize, CQK_SMEM);

    init_slots_kernel<<<BH*KS/8, 256>>>(Sinit);

    // QKV projection (bf16-split tensor cores) + scatter to heads
    mma_gemm<<<dim3(3072/128, (BB*TT)/128), 256>>>(x, Wqkv, bqkv, nullptr, DD, 0, 3072);
    khat_kernel<<<BHT/8, 256>>>();

    // sequential chunk scan
    for (int ch = 0; ch < NCH; ch++) {
        chunk_qk_kernel<<<dim3(8, BH), 256, CQK_SMEM>>>(ch, temp);
        chunk_update_kernel<<<dim3(64, BH), 256>>>(ch);
    }

    // local sliding-window attention
    local_attn_kernel<<<dim3(TT/128, BH), 256>>>();

    // output projection (bf16-split tensor cores, fused reads+local)
    mma_gemm<<<dim3(DD/128, (BB*TT)/128), 256>>>(nullptr, Wo, bo, out, DD, 1, DD);

    (void)in_sizes; (void)n_in; (void)out_size;
}

// round 8
// speedup vs baseline: 2.3216x; 1.4941x over previous
#include <cuda_runtime.h>
#include <cuda_bf16.h>
#include <math.h>

// ---------------- problem constants ----------------
#define BB   2
#define TT   2048
#define DD   1024
#define HH   8
#define DH   128
#define KS   512
#define KRR  16
#define CH   128
#define NCH  16
#define ETA_C    0.1f
#define FORGET_C 0.01f
#define SCALE_C  0.08838834764831845f

#define BHT (BB*HH*TT)
#define BH  (BB*HH)

// ---------------- scratch ----------------
__device__ float g_q   [BB*HH*TT*DH];
__device__ float g_k   [BB*HH*TT*DH];
__device__ float g_v   [BB*HH*TT*DH];
__device__ float g_khat[BB*HH*TT*DH];
__device__ float g_reads[BB*HH*TT*DH];
__device__ float g_local[BB*HH*TT*DH];
__device__ float g_slotk[BB*HH*KS*DH];
__device__ float g_slotv[BB*HH*KS*DH];
__device__ __nv_bfloat16 g_skh[BB*HH*KS*DH];   // slot_k bf16 hi
__device__ __nv_bfloat16 g_skl[BB*HH*KS*DH];   // slot_k bf16 lo
__device__ int   g_eidx [BB*HH*CH*KRR];
__device__ float g_ewp  [BB*HH*CH*KRR];
__device__ float g_eproj[BB*HH*CH*KRR];

// fused A-load for final projection: A = reads + local, head-interleaved
__device__ __forceinline__ float4 fused_load(int row, int col)
{
    int b = row >> 11, t = row & 2047;
    int h = col >> 7,  e = col & 127;
    int idx = (((b*HH + h)*TT) + t)*DH + e;
    float4 r = *(const float4*)&g_reads[idx];
    float4 l = *(const float4*)&g_local[idx];
    return make_float4(r.x+l.x, r.y+l.y, r.z+l.z, r.w+l.w);
}

// ---------------- bf16-split MMA primitives ----------------
__device__ __forceinline__ void mma16816(float* d, const unsigned* a, const unsigned* b)
{
    asm volatile(
        "mma.sync.aligned.m16n8k16.row.col.f32.bf16.bf16.f32 "
        "{%0,%1,%2,%3}, {%4,%5,%6,%7}, {%8,%9}, {%0,%1,%2,%3};\n"
        : "+f"(d[0]), "+f"(d[1]), "+f"(d[2]), "+f"(d[3])
        : "r"(a[0]), "r"(a[1]), "r"(a[2]), "r"(a[3]), "r"(b[0]), "r"(b[1]));
}

__device__ __forceinline__ void split_store(float4 v, __nv_bfloat16* Hp, __nv_bfloat16* Lp)
{
    float f[4] = {v.x, v.y, v.z, v.w};
#pragma unroll
    for (int p = 0; p < 2; p++) {
        __nv_bfloat16 h0 = __float2bfloat16(f[2*p]);
        __nv_bfloat16 h1 = __float2bfloat16(f[2*p+1]);
        __nv_bfloat16 l0 = __float2bfloat16(f[2*p]   - __bfloat162float(h0));
        __nv_bfloat16 l1 = __float2bfloat16(f[2*p+1] - __bfloat162float(h1));
        unsigned hp = (unsigned)__bfloat16_as_ushort(h0) | ((unsigned)__bfloat16_as_ushort(h1) << 16);
        unsigned lp = (unsigned)__bfloat16_as_ushort(l0) | ((unsigned)__bfloat16_as_ushort(l1) << 16);
        *(unsigned*)(Hp + 2*p) = hp;
        *(unsigned*)(Lp + 2*p) = lp;
    }
}

__device__ __forceinline__ void pack_hl(float a, float b, unsigned& h, unsigned& l)
{
    __nv_bfloat16 ha = __float2bfloat16(a), hb = __float2bfloat16(b);
    __nv_bfloat16 la = __float2bfloat16(a - __bfloat162float(ha));
    __nv_bfloat16 lb = __float2bfloat16(b - __bfloat162float(hb));
    h = (unsigned)__bfloat16_as_ushort(ha) | ((unsigned)__bfloat16_as_ushort(hb) << 16);
    l = (unsigned)__bfloat16_as_ushort(la) | ((unsigned)__bfloat16_as_ushort(lb) << 16);
}

__device__ __forceinline__ void write_c(int mode, float* Cout, int Ncols,
                                        int row, int col, float val)
{
    if (mode == 0) {
        int which = col >> 10;
        int h = (col >> 7) & 7;
        int e = col & 127;
        int b = row >> 11;
        int t = row & 2047;
        float* dst = (which == 0) ? g_q : (which == 1) ? g_k : g_v;
        dst[(((b*HH + h)*TT) + t)*DH + e] = val;
    } else {
        Cout[row * Ncols + col] = val;
    }
}

// ---------------- big GEMMs (qkv / out-proj), bf16-split ----------------
__global__ __launch_bounds__(256)
void mma_gemm(const float* __restrict__ A, const float* __restrict__ Bm,
              const float* __restrict__ bias, float* __restrict__ Cout,
              int Kdim, int mode, int Ncols)
{
    __shared__ __nv_bfloat16 Ah[128][24], Al[128][24];
    __shared__ __nv_bfloat16 Bh[128][24], Bl[128][24];

    int bm = blockIdx.y * 128, bn = blockIdx.x * 128;
    int tid = threadIdx.x;
    int warp = tid >> 5, lane = tid & 31;
    int wm = warp >> 2, wn = warp & 3;
    int lr = lane >> 2, lc = lane & 3;

    int srow = tid >> 1;
    int sk   = (tid & 1) * 8;

    float acc[4][4][4];
#pragma unroll
    for (int i = 0; i < 4; i++)
#pragma unroll
        for (int j = 0; j < 4; j++)
#pragma unroll
            for (int r = 0; r < 4; r++) acc[i][j][r] = 0.f;

    int arow = bm + srow, brow = bn + srow;
    float4 a0v = mode ? fused_load(arow, sk)     : *(const float4*)(A + arow*Kdim + sk);
    float4 a1v = mode ? fused_load(arow, sk + 4) : *(const float4*)(A + arow*Kdim + sk + 4);
    float4 b0v = *(const float4*)(Bm + brow*Kdim + sk);
    float4 b1v = *(const float4*)(Bm + brow*Kdim + sk + 4);

    for (int kp = 0; kp < Kdim; kp += 16) {
        __syncthreads();
        split_store(a0v, &Ah[srow][sk],   &Al[srow][sk]);
        split_store(a1v, &Ah[srow][sk+4], &Al[srow][sk+4]);
        split_store(b0v, &Bh[srow][sk],   &Bl[srow][sk]);
        split_store(b1v, &Bh[srow][sk+4], &Bl[srow][sk+4]);
        __syncthreads();
        if (kp + 16 < Kdim) {
            int kn = kp + 16;
            a0v = mode ? fused_load(arow, kn + sk)     : *(const float4*)(A + arow*Kdim + kn + sk);
            a1v = mode ? fused_load(arow, kn + sk + 4) : *(const float4*)(A + arow*Kdim + kn + sk + 4);
            b0v = *(const float4*)(Bm + brow*Kdim + kn + sk);
            b1v = *(const float4*)(Bm + brow*Kdim + kn + sk + 4);
        }

        unsigned Afh[4][4], Afl[4][4], Bfh[4][2], Bfl[4][2];
#pragma unroll
        for (int mi = 0; mi < 4; mi++) {
            int r = wm*64 + mi*16 + lr;
            Afh[mi][0] = *(const unsigned*)&Ah[r][lc*2];
            Afh[mi][1] = *(const unsigned*)&Ah[r+8][lc*2];
            Afh[mi][2] = *(const unsigned*)&Ah[r][lc*2+8];
            Afh[mi][3] = *(const unsigned*)&Ah[r+8][lc*2+8];
            Afl[mi][0] = *(const unsigned*)&Al[r][lc*2];
            Afl[mi][1] = *(const unsigned*)&Al[r+8][lc*2];
            Afl[mi][2] = *(const unsigned*)&Al[r][lc*2+8];
            Afl[mi][3] = *(const unsigned*)&Al[r+8][lc*2+8];
        }
#pragma unroll
        for (int ni = 0; ni < 4; ni++) {
            int n = wn*32 + ni*8 + lr;
            Bfh[ni][0] = *(const unsigned*)&Bh[n][lc*2];
            Bfh[ni][1] = *(const unsigned*)&Bh[n][lc*2+8];
            Bfl[ni][0] = *(const unsigned*)&Bl[n][lc*2];
            Bfl[ni][1] = *(const unsigned*)&Bl[n][lc*2+8];
        }
#pragma unroll
        for (int mi = 0; mi < 4; mi++)
#pragma unroll
            for (int ni = 0; ni < 4; ni++) {
                mma16816(acc[mi][ni], Afh[mi], Bfh[ni]);
                mma16816(acc[mi][ni], Afh[mi], Bfl[ni]);
                mma16816(acc[mi][ni], Afl[mi], Bfh[ni]);
            }
    }

#pragma unroll
    for (int mi = 0; mi < 4; mi++)
#pragma unroll
        for (int ni = 0; ni < 4; ni++) {
            int row0 = bm + wm*64 + mi*16 + lr;
            int col0 = bn + wn*32 + ni*8 + lc*2;
            write_c(mode, Cout, Ncols, row0,   col0,   acc[mi][ni][0] + bias[col0]);
            write_c(mode, Cout, Ncols, row0,   col0+1, acc[mi][ni][1] + bias[col0+1]);
            write_c(mode, Cout, Ncols, row0+8, col0,   acc[mi][ni][2] + bias[col0]);
            write_c(mode, Cout, Ncols, row0+8, col0+1, acc[mi][ni][3] + bias[col0+1]);
        }
}

// ---------------- k_hat = l2norm(k) ----------------
__global__ __launch_bounds__(256)
void khat_kernel()
{
    int warp = threadIdx.x >> 5, lane = threadIdx.x & 31;
    int row = blockIdx.x * 8 + warp;
    int base = row * DH;
    float v[4]; float n = 0.f;
#pragma unroll
    for (int i = 0; i < 4; i++) { v[i] = g_k[base + lane + 32*i]; n += v[i]*v[i]; }
#pragma unroll
    for (int off = 16; off; off >>= 1) n += __shfl_xor_sync(0xffffffffu, n, off);
    float inv = 1.0f / (sqrtf(n) + 1e-6f);
#pragma unroll
    for (int i = 0; i < 4; i++) g_khat[base + lane + 32*i] = v[i]*inv;
}

// ---------------- slot init (writes fp32 + bf16 hi/lo) ----------------
__global__ __launch_bounds__(256)
void init_slots_kernel(const float* __restrict__ Sinit)
{
    int warp = threadIdx.x >> 5, lane = threadIdx.x & 31;
    int wid = blockIdx.x * 8 + warp;
    int bh = wid >> 9;
    int s  = wid & 511;
    int h  = bh & 7;
    const float* src = Sinit + s*DD + h*DH;
    float v[4]; float n = 0.f;
#pragma unroll
    for (int i = 0; i < 4; i++) { v[i] = src[lane + 32*i]; n += v[i]*v[i]; }
#pragma unroll
    for (int off = 16; off; off >>= 1) n += __shfl_xor_sync(0xffffffffu, n, off);
    float inv = 1.0f / (sqrtf(n) + 1e-6f);
    int rb = (bh*KS + s)*DH;
#pragma unroll
    for (int i = 0; i < 4; i++) {
        int e = lane + 32*i;
        float kk = v[i]*inv;
        g_slotk[rb + e] = kk;
        g_slotv[rb + e] = v[i];
        __nv_bfloat16 hv = __float2bfloat16(kk);
        g_skh[rb + e] = hv;
        g_skl[rb + e] = __float2bfloat16(kk - __bfloat162float(hv));
    }
}

// ---------------- top-16 + softmax from smem score row ------------------
__device__ __forceinline__
void topk16_smem(const float* __restrict__ row, int lane, int* oi, float* op)
{
    float v[16];
#pragma unroll
    for (int i = 0; i < 16; i++) v[i] = row[i*32 + lane];
    float m = 0.f, sum = 0.f;
#pragma unroll
    for (int it = 0; it < 16; it++) {
        float bv = -INFINITY; int bl = 0;
#pragma unroll
        for (int i = 0; i < 16; i++)
            if (v[i] > bv) { bv = v[i]; bl = i; }
        int bi = bl*32 + lane;
#pragma unroll
        for (int off = 16; off; off >>= 1) {
            float ov = __shfl_xor_sync(0xffffffffu, bv, off);
            int   o2 = __shfl_xor_sync(0xffffffffu, bi, off);
            if (ov > bv || (ov == bv && o2 < bi)) { bv = ov; bi = o2; }
        }
        if (it == 0) m = bv;
        op[it] = __expf(bv - m);
        sum += op[it];
        oi[it] = bi;
        int wl = bi & 31;
        int wloc = bi >> 5;
#pragma unroll
        for (int i = 0; i < 16; i++)
            if (lane == wl && i == wloc) v[i] = -INFINITY;
    }
    float inv = 1.0f / sum;
#pragma unroll
    for (int it = 0; it < 16; it++) op[it] *= inv;
}

// ---------------- fused chunk kernel: MMA scores + topk + read/proj ----
// grid (8, BH), block 512 (16 warps), dynamic smem.
#define AP 136
#define SP 520
#define CQK_SMEM (32*AP*2*2 + 128*AP*2*2 + 32*SP*4)
__global__ __launch_bounds__(512)
void chunk_qk_kernel(int chunk, const float* __restrict__ temp_ptr)
{
    extern __shared__ char smemraw[];
    __nv_bfloat16* Ah = (__nv_bfloat16*)smemraw;   // [32][AP]
    __nv_bfloat16* Al = Ah + 32*AP;
    __nv_bfloat16* Bh = Al + 32*AP;                // [128][AP]
    __nv_bfloat16* Bl = Bh + 128*AP;
    float* scores = (float*)(Bl + 128*AP);         // [32][SP]

    int qt = blockIdx.x, bh = blockIdx.y;
    int q0 = qt * 16;
    int tid = threadIdx.x;
    int warp = tid >> 5, lane = tid & 31;
    int wm = warp >> 3, wn = warp & 7;     // 2 x 8 warp grid: 16 rows x 16 cols per warp per t-tile
    int lr = lane >> 2, lc = lane & 3;

    float fq = SCALE_C / temp_ptr[0];
    int tokrow0 = bh*TT + chunk*CH + q0;

    // load + split A: rows 0-15 q, rows 16-31 khat
    for (int i = tid; i < 32*32; i += 512) {
        int r = i >> 5, c4 = (i & 31)*4;
        const float* src = (r < 16 ? g_q : g_khat) + (tokrow0 + (r & 15))*DH + c4;
        split_store(*(const float4*)src, &Ah[r*AP + c4], &Al[r*AP + c4]);
    }

    int slotbase = bh*KS;

#pragma unroll 1
    for (int t = 0; t < 4; t++) {
        __syncthreads();
        for (int i = tid; i < 128*16; i += 512) {
            int row = i >> 4, seg = (i & 15)*8;
            int gidx = (slotbase + t*128 + row)*DH + seg;
            *(uint4*)&Bh[row*AP + seg] = *(const uint4*)&g_skh[gidx];
            *(uint4*)&Bl[row*AP + seg] = *(const uint4*)&g_skl[gidx];
        }
        __syncthreads();

        float acc[2][4];
#pragma unroll
        for (int n = 0; n < 2; n++)
#pragma unroll
            for (int r = 0; r < 4; r++) acc[n][r] = 0.f;

#pragma unroll
        for (int kt = 0; kt < 8; kt++) {
            int k0 = kt*16;
            unsigned Afh[4], Afl[4];
            int r = wm*16 + lr;
            Afh[0] = *(const unsigned*)&Ah[r*AP + k0 + lc*2];
            Afh[1] = *(const unsigned*)&Ah[(r+8)*AP + k0 + lc*2];
            Afh[2] = *(const unsigned*)&Ah[r*AP + k0 + lc*2 + 8];
            Afh[3] = *(const unsigned*)&Ah[(r+8)*AP + k0 + lc*2 + 8];
            Afl[0] = *(const unsigned*)&Al[r*AP + k0 + lc*2];
            Afl[1] = *(const unsigned*)&Al[(r+8)*AP + k0 + lc*2];
            Afl[2] = *(const unsigned*)&Al[r*AP + k0 + lc*2 + 8];
            Afl[3] = *(const unsigned*)&Al[(r+8)*AP + k0 + lc*2 + 8];
#pragma unroll
            for (int n = 0; n < 2; n++) {
                int nr = wn*16 + n*8 + lr;
                unsigned Bf0[2], Bf1[2];
                Bf0[0] = *(const unsigned*)&Bh[nr*AP + k0 + lc*2];
                Bf0[1] = *(const unsigned*)&Bh[nr*AP + k0 + lc*2 + 8];
                Bf1[0] = *(const unsigned*)&Bl[nr*AP + k0 + lc*2];
                Bf1[1] = *(const unsigned*)&Bl[nr*AP + k0 + lc*2 + 8];
                mma16816(acc[n], Afh, Bf0);
                mma16816(acc[n], Afh, Bf1);
                mma16816(acc[n], Afl, Bf0);
            }
        }
        float factor = (wm == 0) ? fq : 1.0f;
#pragma unroll
        for (int n = 0; n < 2; n++) {
            int col = t*128 + wn*16 + n*8 + lc*2;
            int row0 = wm*16 + lr;
            scores[row0*SP + col]       = acc[n][0]*factor;
            scores[row0*SP + col + 1]   = acc[n][1]*factor;
            scores[(row0+8)*SP + col]   = acc[n][2]*factor;
            scores[(row0+8)*SP + col+1] = acc[n][3]*factor;
        }
    }
    __syncthreads();

    // topk + read / proj.  warps 0-7: q queries (2 each); warps 8-15: khat.
    bool isq = warp < 8;
#pragma unroll 1
    for (int j = 0; j < 2; j++) {
        int qi = (warp & 7)*2 + j;
        int srow = isq ? qi : (16 + qi);
        int oi[16]; float op[16];
        topk16_smem(&scores[srow*SP], lane, oi, op);

        int tbase = (tokrow0 + qi)*DH;

        if (isq) {
            float4 acc = make_float4(0.f, 0.f, 0.f, 0.f);
#pragma unroll
            for (int k = 0; k < 16; k++) {
                float4 vv = *(const float4*)&g_slotv[(slotbase + oi[k])*DH + lane*4];
                acc.x += op[k]*vv.x; acc.y += op[k]*vv.y;
                acc.z += op[k]*vv.z; acc.w += op[k]*vv.w;
            }
            *(float4*)&g_reads[tbase + lane*4] = acc;
        } else {
            float4 vv = *(const float4*)&g_v[tbase + lane*4];
            int eb = (bh*CH + q0 + qi)*KRR;
#pragma unroll
            for (int k = 0; k < 16; k++) {
                float4 kk = *(const float4*)&g_slotk[(slotbase + oi[k])*DH + lane*4];
                float d = vv.x*kk.x + vv.y*kk.y + vv.z*kk.z + vv.w*kk.w;
#pragma unroll
                for (int off = 16; off; off >>= 1)
                    d += __shfl_xor_sync(0xffffffffu, d, off);
                if (lane == 0) {
                    g_eidx[eb + k]  = oi[k];
                    g_ewp[eb + k]   = op[k];
                    g_eproj[eb + k] = d;
                }
            }
        }
    }
}

// ---------------- deterministic slot update (writes fp32 + bf16) --------
__global__ __launch_bounds__(256)
void chunk_update_kernel(int chunk)
{
    int bh = blockIdx.y;
    int tid = threadIdx.x;
    int warp = tid >> 5, lane = tid & 31;
    int s = blockIdx.x * 8 + warp;

    __shared__ int   sidx[CH*KRR];
    __shared__ float swp [CH*KRR];
    __shared__ float sprj[CH*KRR];
    int ebase = bh*CH*KRR;
    for (int j = tid; j < CH*KRR; j += 256) {
        sidx[j] = g_eidx[ebase + j];
        swp[j]  = g_ewp[ebase + j];
        sprj[j] = g_eproj[ebase + j];
    }
    __syncthreads();

    int tokbase = (bh*TT + chunk*CH)*DH;

    float accv[4] = {0,0,0,0};
    float acck[4] = {0,0,0,0};
    float swpsum = 0.f, swpp = 0.f;
    for (int b0 = 0; b0 < CH*KRR; b0 += 32) {
        bool mt = (sidx[b0 + lane] == s);
        unsigned bal = __ballot_sync(0xffffffffu, mt);
        while (bal) {
            int jj = b0 + (__ffs(bal) - 1);
            bal &= bal - 1;
            float wp = swp[jj];
            float pj = sprj[jj];
            int cc = jj >> 4;
            const float* vr = g_v    + tokbase + cc*DH;
            const float* kr = g_khat + tokbase + cc*DH;
#pragma unroll
            for (int i = 0; i < 4; i++) {
                int e = lane + 32*i;
                accv[i] += wp * vr[e];
                acck[i] += wp * kr[e];
            }
            swpsum += wp;
            swpp   += wp * pj;
        }
    }
    int rb = (bh*KS + s)*DH;
    float* kd = g_slotk + rb;
    float* vd = g_slotv + rb;
    float nk[4]; float nsum = 0.f;
#pragma unroll
    for (int i = 0; i < 4; i++) {
        int e = lane + 32*i;
        float ok = kd[e];
        float nv = (1.0f - FORGET_C) * vd[e] + ETA_C * (accv[i] - swpp * ok);
        vd[e] = nv;
        nk[i] = ok + ETA_C * (acck[i] - swpsum * ok);
        nsum += nk[i]*nk[i];
    }
#pragma unroll
    for (int off = 16; off; off >>= 1) nsum += __shfl_xor_sync(0xffffffffu, nsum, off);
    float inv = 1.0f / (sqrtf(nsum) + 1e-6f);
#pragma unroll
    for (int i = 0; i < 4; i++) {
        int e = lane + 32*i;
        float val = nk[i]*inv;
        kd[e] = val;
        __nv_bfloat16 hv = __float2bfloat16(val);
        g_skh[rb + e] = hv;
        g_skl[rb + e] = __float2bfloat16(val - __bfloat162float(hv));
    }
}

// ---------------- local sliding-window attention (tensor cores) --------
// grid (TT/64=32, BH), block 128 (4 warps). 64 queries/block, 16/warp.
// Online-softmax flash loop over 64-key tiles in [max(0,q0-512), q0+63].
#define LKP 136
#define LSMEM (4*64*LKP*2)
__global__ __launch_bounds__(128)
void local_mma_kernel()
{
    extern __shared__ __nv_bfloat16 lsm[];
    __nv_bfloat16* Ksh = lsm;              // [64][LKP]
    __nv_bfloat16* Ksl = Ksh + 64*LKP;
    __nv_bfloat16* Vsh = Ksl + 64*LKP;     // [64][LKP]
    __nv_bfloat16* Vsl = Vsh + 64*LKP;
    __nv_bfloat16* Qh = Ksh;               // Q staged in K/V region (transient)
    __nv_bfloat16* Ql = Ksl;

    int q0 = blockIdx.x * 64, bh = blockIdx.y;
    int tid = threadIdx.x, warp = tid >> 5, lane = tid & 31;

    // stage Q (64 x 128) split
    for (int i = tid; i < 64*32; i += 128) {
        int r = i >> 5, c4 = (i & 31)*4;
        split_store(*(const float4*)&g_q[(bh*TT + q0 + r)*DH + c4],
                    &Qh[r*LKP + c4], &Ql[r*LKP + c4]);
    }
    __syncthreads();

    // Q fragments (resident in registers)
    unsigned aqh[8][4], aql[8][4];
    int r0 = warp*16 + (lane >> 2);
#pragma unroll
    for (int kf = 0; kf < 8; kf++) {
        int c = kf*16 + (lane & 3)*2;
        aqh[kf][0] = *(const unsigned*)&Qh[r0*LKP + c];
        aqh[kf][1] = *(const unsigned*)&Qh[(r0+8)*LKP + c];
        aqh[kf][2] = *(const unsigned*)&Qh[r0*LKP + c + 8];
        aqh[kf][3] = *(const unsigned*)&Qh[(r0+8)*LKP + c + 8];
        aql[kf][0] = *(const unsigned*)&Ql[r0*LKP + c];
        aql[kf][1] = *(const unsigned*)&Ql[(r0+8)*LKP + c];
        aql[kf][2] = *(const unsigned*)&Ql[r0*LKP + c + 8];
        aql[kf][3] = *(const unsigned*)&Ql[(r0+8)*LKP + c + 8];
    }

    float m0 = -1e30f, l0 = 0.f, m1 = -1e30f, l1 = 0.f;
    float o[16][4];
#pragma unroll
    for (int i = 0; i < 16; i++)
#pragma unroll
        for (int r = 0; r < 4; r++) o[i][r] = 0.f;

    int qg0 = q0 + warp*16 + (lane >> 2);
    int qg1 = qg0 + 8;
    int kstart = q0 - 512; if (kstart < 0) kstart = 0;

    unsigned vbh = (unsigned)__cvta_generic_to_shared(Vsh);
    unsigned vbl = (unsigned)__cvta_generic_to_shared(Vsl);

#pragma unroll 1
    for (int kt = kstart; kt <= q0; kt += 64) {
        __syncthreads();
        // stage K and V tiles split
        for (int i = tid; i < 64*32; i += 128) {
            int r = i >> 5, c4 = (i & 31)*4;
            int gi = (bh*TT + kt + r)*DH + c4;
            split_store(*(const float4*)&g_k[gi], &Ksh[r*LKP + c4], &Ksl[r*LKP + c4]);
            split_store(*(const float4*)&g_v[gi], &Vsh[r*LKP + c4], &Vsl[r*LKP + c4]);
        }
        __syncthreads();

        // S = Q K^T (bf16-split, 3 mma)
        float s[8][4];
#pragma unroll
        for (int n = 0; n < 8; n++)
#pragma unroll
            for (int r = 0; r < 4; r++) s[n][r] = 0.f;
#pragma unroll
        for (int kf = 0; kf < 8; kf++) {
            int c = kf*16 + (lane & 3)*2;
#pragma unroll
            for (int nf = 0; nf < 8; nf++) {
                int key = nf*8 + (lane >> 2);
                unsigned b0[2], b1[2];
                b0[0] = *(const unsigned*)&Ksh[key*LKP + c];
                b0[1] = *(const unsigned*)&Ksh[key*LKP + c + 8];
                b1[0] = *(const unsigned*)&Ksl[key*LKP + c];
                b1[1] = *(const unsigned*)&Ksl[key*LKP + c + 8];
                mma16816(s[nf], aqh[kf], b0);
                mma16816(s[nf], aqh[kf], b1);
                mma16816(s[nf], aql[kf], b0);
            }
        }

        // mask + scale, row max
        float rm0 = -1e30f, rm1 = -1e30f;
#pragma unroll
        for (int nf = 0; nf < 8; nf++) {
            int kgb = kt + nf*8 + (lane & 3)*2;
#pragma unroll
            for (int e = 0; e < 4; e++) {
                int kg = kgb + (e & 1);
                int qg = (e < 2) ? qg0 : qg1;
                float sv = s[nf][e] * SCALE_C;
                bool ok = (kg <= qg) && (kg > qg - 512);
                sv = ok ? sv : -1e30f;
                s[nf][e] = sv;
                if (e < 2) rm0 = fmaxf(rm0, sv); else rm1 = fmaxf(rm1, sv);
            }
        }
        rm0 = fmaxf(rm0, __shfl_xor_sync(0xffffffffu, rm0, 1));
        rm0 = fmaxf(rm0, __shfl_xor_sync(0xffffffffu, rm0, 2));
        rm1 = fmaxf(rm1, __shfl_xor_sync(0xffffffffu, rm1, 1));
        rm1 = fmaxf(rm1, __shfl_xor_sync(0xffffffffu, rm1, 2));
        float mn0 = fmaxf(m0, rm0), mn1 = fmaxf(m1, rm1);
        float c0 = __expf(m0 - mn0), c1 = __expf(m1 - mn1);
        m0 = mn0; m1 = mn1;

        float ps0 = 0.f, ps1 = 0.f;
#pragma unroll
        for (int nf = 0; nf < 8; nf++)
#pragma unroll
            for (int e = 0; e < 4; e++) {
                float sv = s[nf][e];
                float p = __expf(sv - ((e < 2) ? mn0 : mn1));
                p = (sv > -1e29f) ? p : 0.f;
                s[nf][e] = p;
                if (e < 2) ps0 += p; else ps1 += p;
            }
        ps0 += __shfl_xor_sync(0xffffffffu, ps0, 1);
        ps0 += __shfl_xor_sync(0xffffffffu, ps0, 2);
        ps1 += __shfl_xor_sync(0xffffffffu, ps1, 1);
        ps1 += __shfl_xor_sync(0xffffffffu, ps1, 2);
        l0 = l0*c0 + ps0;
        l1 = l1*c1 + ps1;

        // rescale O
#pragma unroll
        for (int n = 0; n < 16; n++) {
            o[n][0] *= c0; o[n][1] *= c0; o[n][2] *= c1; o[n][3] *= c1;
        }

        // pack P (hi/lo) as A-operand fragments for PV
        unsigned ph[4][4], pl[4][4];
#pragma unroll
        for (int kf2 = 0; kf2 < 4; kf2++) {
            pack_hl(s[2*kf2][0],   s[2*kf2][1],   ph[kf2][0], pl[kf2][0]);
            pack_hl(s[2*kf2][2],   s[2*kf2][3],   ph[kf2][1], pl[kf2][1]);
            pack_hl(s[2*kf2+1][0], s[2*kf2+1][1], ph[kf2][2], pl[kf2][2]);
            pack_hl(s[2*kf2+1][2], s[2*kf2+1][3], ph[kf2][3], pl[kf2][3]);
        }

        // PV: O += P * V   (V B-frags via ldmatrix.x2.trans from [key][dh])
#pragma unroll
        for (int nf2 = 0; nf2 < 16; nf2++) {
#pragma unroll
            for (int kf2 = 0; kf2 < 4; kf2++) {
                unsigned off = ((unsigned)((kf2*16 + (lane & 15))*LKP + nf2*8)) * 2u;
                unsigned bv[2], bw[2];
                asm volatile(
                    "ldmatrix.sync.aligned.m8n8.x2.trans.shared.b16 {%0,%1}, [%2];"
                    : "=r"(bv[0]), "=r"(bv[1]) : "r"(vbh + off));
                asm volatile(
                    "ldmatrix.sync.aligned.m8n8.x2.trans.shared.b16 {%0,%1}, [%2];"
                    : "=r"(bw[0]), "=r"(bw[1]) : "r"(vbl + off));
                mma16816(o[nf2], ph[kf2], bv);
                mma16816(o[nf2], pl[kf2], bv);
                mma16816(o[nf2], ph[kf2], bw);
            }
        }
    }

    float iv0 = 1.0f / l0, iv1 = 1.0f / l1;
    float* out0 = g_local + (bh*TT + qg0)*DH;
    float* out1 = g_local + (bh*TT + qg1)*DH;
#pragma unroll
    for (int n = 0; n < 16; n++) {
        int col = n*8 + (lane & 3)*2;
        *(float2*)(out0 + col) = make_float2(o[n][0]*iv0, o[n][1]*iv0);
        *(float2*)(out1 + col) = make_float2(o[n][2]*iv1, o[n][3]*iv1);
    }
}

// ---------------- launch ----------------
extern "C" void kernel_launch(void* const* d_in, const int* in_sizes, int n_in,
                              void* d_out, int out_size)
{
    const float* x     = (const float*)d_in[0];
    const float* Wqkv  = (const float*)d_in[1];
    const float* bqkv  = (const float*)d_in[2];
    const float* Wo    = (const float*)d_in[3];
    const float* bo    = (const float*)d_in[4];
    const float* Sinit = (const float*)d_in[5];
    const float* temp  = (const float*)d_in[6];
    float* out = (float*)d_out;

    cudaFuncSetAttribute(chunk_qk_kernel,
                         cudaFuncAttributeMaxDynamicSharedMemorySize, CQK_SMEM);
    cudaFuncSetAttribute(local_mma_kernel,
                         cudaFuncAttributeMaxDynamicSharedMemorySize, LSMEM);

    init_slots_kernel<<<BH*KS/8, 256>>>(Sinit);

    // QKV projection (bf16-split tensor cores) + scatter to heads
    mma_gemm<<<dim3(3072/128, (BB*TT)/128), 256>>>(x, Wqkv, bqkv, nullptr, DD, 0, 3072);
    khat_kernel<<<BHT/8, 256>>>();

    // sequential chunk scan
    for (int ch = 0; ch < NCH; ch++) {
        chunk_qk_kernel<<<dim3(8, BH), 512, CQK_SMEM>>>(ch, temp);
        chunk_update_kernel<<<dim3(64, BH), 256>>>(ch);
    }

    // local sliding-window attention (tensor cores)
    local_mma_kernel<<<dim3(TT/64, BH), 128, LSMEM>>>();

    // output projection (bf16-split tensor cores, fused reads+local)
    mma_gemm<<<dim3(DD/128, (BB*TT)/128), 256>>>(nullptr, Wo, bo, out, DD, 1, DD);

    (void)in_sizes; (void)n_in; (void)out_size;
}

// round 10
// speedup vs baseline: 2.5587x; 1.1021x over previous
#include <cuda_runtime.h>
#include <cuda_bf16.h>
#include <math.h>

// ---------------- problem constants ----------------
#define BB   2
#define TT   2048
#define DD   1024
#define HH   8
#define DH   128
#define KS   512
#define KRR  16
#define CH   128
#define NCH  16
#define ETA_C    0.1f
#define FORGET_C 0.01f
#define SCALE_C  0.08838834764831845f

#define BHT (BB*HH*TT)
#define BH  (BB*HH)

// ---------------- scratch ----------------
__device__ float g_q   [BB*HH*TT*DH];
__device__ float g_k   [BB*HH*TT*DH];
__device__ float g_v   [BB*HH*TT*DH];
__device__ float g_khat[BB*HH*TT*DH];
__device__ float g_reads[BB*HH*TT*DH];
__device__ float g_local[BB*HH*TT*DH];
__device__ float g_slotk[BB*HH*KS*DH];
__device__ float g_slotv[BB*HH*KS*DH];
__device__ __nv_bfloat16 g_skh[BB*HH*KS*DH];
__device__ __nv_bfloat16 g_skl[BB*HH*KS*DH];
// pre-split bf16 hi/lo copies (written once, streamed many times)
__device__ __nv_bfloat16 g_qh[BB*HH*TT*DH], g_ql[BB*HH*TT*DH];
__device__ __nv_bfloat16 g_kh[BB*HH*TT*DH], g_kl[BB*HH*TT*DH];
__device__ __nv_bfloat16 g_vh[BB*HH*TT*DH], g_vl[BB*HH*TT*DH];
__device__ __nv_bfloat16 g_khh[BB*HH*TT*DH], g_khl[BB*HH*TT*DH];
__device__ int   g_eidx [BB*HH*CH*KRR];
__device__ float g_ewp  [BB*HH*CH*KRR];
__device__ float g_eproj[BB*HH*CH*KRR];

// ---------------- cp.async helpers ----------------
__device__ __forceinline__ void cpa16(void* dst, const void* src)
{
    unsigned d = (unsigned)__cvta_generic_to_shared(dst);
    asm volatile("cp.async.cg.shared.global [%0], [%1], 16;\n"
                 :: "r"(d), "l"(__cvta_generic_to_global(src)));
}
#define CP_COMMIT asm volatile("cp.async.commit_group;\n" ::: "memory")
#define CP_WAIT(n) asm volatile("cp.async.wait_group %0;\n" :: "n"(n) : "memory")

// fused A-load for final projection: A = reads + local, head-interleaved
__device__ __forceinline__ float4 fused_load(int row, int col)
{
    int b = row >> 11, t = row & 2047;
    int h = col >> 7,  e = col & 127;
    int idx = (((b*HH + h)*TT) + t)*DH + e;
    float4 r = *(const float4*)&g_reads[idx];
    float4 l = *(const float4*)&g_local[idx];
    return make_float4(r.x+l.x, r.y+l.y, r.z+l.z, r.w+l.w);
}

// ---------------- bf16-split MMA primitives ----------------
__device__ __forceinline__ void mma16816(float* d, const unsigned* a, const unsigned* b)
{
    asm volatile(
        "mma.sync.aligned.m16n8k16.row.col.f32.bf16.bf16.f32 "
        "{%0,%1,%2,%3}, {%4,%5,%6,%7}, {%8,%9}, {%0,%1,%2,%3};\n"
        : "+f"(d[0]), "+f"(d[1]), "+f"(d[2]), "+f"(d[3])
        : "r"(a[0]), "r"(a[1]), "r"(a[2]), "r"(a[3]), "r"(b[0]), "r"(b[1]));
}

__device__ __forceinline__ void pack_hl(float a, float b, unsigned& h, unsigned& l)
{
    __nv_bfloat16 ha = __float2bfloat16(a), hb = __float2bfloat16(b);
    __nv_bfloat16 la = __float2bfloat16(a - __bfloat162float(ha));
    __nv_bfloat16 lb = __float2bfloat16(b - __bfloat162float(hb));
    h = (unsigned)__bfloat16_as_ushort(ha) | ((unsigned)__bfloat16_as_ushort(hb) << 16);
    l = (unsigned)__bfloat16_as_ushort(la) | ((unsigned)__bfloat16_as_ushort(lb) << 16);
}

__device__ __forceinline__ void split_store(float4 v, __nv_bfloat16* Hp, __nv_bfloat16* Lp)
{
    unsigned h0, l0, h1, l1;
    pack_hl(v.x, v.y, h0, l0);
    pack_hl(v.z, v.w, h1, l1);
    *(unsigned*)(Hp)     = h0; *(unsigned*)(Hp + 2) = h1;
    *(unsigned*)(Lp)     = l0; *(unsigned*)(Lp + 2) = l1;
}

// epilogue pair-store: mode 0 -> qkv scatter + hi/lo copies; mode 1 -> Cout
__device__ __forceinline__ void write_c2(int mode, float* Cout, int Ncols,
                                         int row, int col, float v0, float v1)
{
    if (mode == 0) {
        int which = col >> 10;
        int h = (col >> 7) & 7;
        int e = col & 127;
        int b = row >> 11;
        int t = row & 2047;
        int idx = (((b*HH + h)*TT) + t)*DH + e;
        float* dst = (which == 0) ? g_q : (which == 1) ? g_k : g_v;
        *(float2*)&dst[idx] = make_float2(v0, v1);
        __nv_bfloat16* dh = (which == 0) ? g_qh : (which == 1) ? g_kh : g_vh;
        __nv_bfloat16* dl = (which == 0) ? g_ql : (which == 1) ? g_kl : g_vl;
        unsigned hp, lp; pack_hl(v0, v1, hp, lp);
        *(unsigned*)&dh[idx] = hp;
        *(unsigned*)&dl[idx] = lp;
    } else {
        *(float2*)&Cout[row * Ncols + col] = make_float2(v0, v1);
    }
}

// ---------------- big GEMMs (qkv / out-proj), bf16-split ----------------
__global__ __launch_bounds__(256)
void mma_gemm(const float* __restrict__ A, const float* __restrict__ Bm,
              const float* __restrict__ bias, float* __restrict__ Cout,
              int Kdim, int mode, int Ncols)
{
    __shared__ __nv_bfloat16 Ah[128][24], Al[128][24];
    __shared__ __nv_bfloat16 Bh[128][24], Bl[128][24];

    int bm = blockIdx.y * 128, bn = blockIdx.x * 128;
    int tid = threadIdx.x;
    int warp = tid >> 5, lane = tid & 31;
    int wm = warp >> 2, wn = warp & 3;
    int lr = lane >> 2, lc = lane & 3;

    int srow = tid >> 1;
    int sk   = (tid & 1) * 8;

    float acc[4][4][4];
#pragma unroll
    for (int i = 0; i < 4; i++)
#pragma unroll
        for (int j = 0; j < 4; j++)
#pragma unroll
            for (int r = 0; r < 4; r++) acc[i][j][r] = 0.f;

    int arow = bm + srow, brow = bn + srow;
    float4 a0v = mode ? fused_load(arow, sk)     : *(const float4*)(A + arow*Kdim + sk);
    float4 a1v = mode ? fused_load(arow, sk + 4) : *(const float4*)(A + arow*Kdim + sk + 4);
    float4 b0v = *(const float4*)(Bm + brow*Kdim + sk);
    float4 b1v = *(const float4*)(Bm + brow*Kdim + sk + 4);

    for (int kp = 0; kp < Kdim; kp += 16) {
        __syncthreads();
        split_store(a0v, &Ah[srow][sk],   &Al[srow][sk]);
        split_store(a1v, &Ah[srow][sk+4], &Al[srow][sk+4]);
        split_store(b0v, &Bh[srow][sk],   &Bl[srow][sk]);
        split_store(b1v, &Bh[srow][sk+4], &Bl[srow][sk+4]);
        __syncthreads();
        if (kp + 16 < Kdim) {
            int kn = kp + 16;
            a0v = mode ? fused_load(arow, kn + sk)     : *(const float4*)(A + arow*Kdim + kn + sk);
            a1v = mode ? fused_load(arow, kn + sk + 4) : *(const float4*)(A + arow*Kdim + kn + sk + 4);
            b0v = *(const float4*)(Bm + brow*Kdim + kn + sk);
            b1v = *(const float4*)(Bm + brow*Kdim + kn + sk + 4);
        }

        unsigned Afh[4][4], Afl[4][4], Bfh[4][2], Bfl[4][2];
#pragma unroll
        for (int mi = 0; mi < 4; mi++) {
            int r = wm*64 + mi*16 + lr;
            Afh[mi][0] = *(const unsigned*)&Ah[r][lc*2];
            Afh[mi][1] = *(const unsigned*)&Ah[r+8][lc*2];
            Afh[mi][2] = *(const unsigned*)&Ah[r][lc*2+8];
            Afh[mi][3] = *(const unsigned*)&Ah[r+8][lc*2+8];
            Afl[mi][0] = *(const unsigned*)&Al[r][lc*2];
            Afl[mi][1] = *(const unsigned*)&Al[r+8][lc*2];
            Afl[mi][2] = *(const unsigned*)&Al[r][lc*2+8];
            Afl[mi][3] = *(const unsigned*)&Al[r+8][lc*2+8];
        }
#pragma unroll
        for (int ni = 0; ni < 4; ni++) {
            int n = wn*32 + ni*8 + lr;
            Bfh[ni][0] = *(const unsigned*)&Bh[n][lc*2];
            Bfh[ni][1] = *(const unsigned*)&Bh[n][lc*2+8];
            Bfl[ni][0] = *(const unsigned*)&Bl[n][lc*2];
            Bfl[ni][1] = *(const unsigned*)&Bl[n][lc*2+8];
        }
#pragma unroll
        for (int mi = 0; mi < 4; mi++)
#pragma unroll
            for (int ni = 0; ni < 4; ni++) {
                mma16816(acc[mi][ni], Afh[mi], Bfh[ni]);
                mma16816(acc[mi][ni], Afh[mi], Bfl[ni]);
                mma16816(acc[mi][ni], Afl[mi], Bfh[ni]);
            }
    }

#pragma unroll
    for (int mi = 0; mi < 4; mi++)
#pragma unroll
        for (int ni = 0; ni < 4; ni++) {
            int row0 = bm + wm*64 + mi*16 + lr;
            int col0 = bn + wn*32 + ni*8 + lc*2;
            write_c2(mode, Cout, Ncols, row0,   col0, acc[mi][ni][0] + bias[col0],
                                               acc[mi][ni][1] + bias[col0+1]);
            write_c2(mode, Cout, Ncols, row0+8, col0, acc[mi][ni][2] + bias[col0],
                                               acc[mi][ni][3] + bias[col0+1]);
        }
}

// ---------------- k_hat = l2norm(k) (+ hi/lo) ----------------
__global__ __launch_bounds__(256)
void khat_kernel()
{
    int warp = threadIdx.x >> 5, lane = threadIdx.x & 31;
    int row = blockIdx.x * 8 + warp;
    int base = row * DH;
    float v[4]; float n = 0.f;
#pragma unroll
    for (int i = 0; i < 4; i++) { v[i] = g_k[base + lane + 32*i]; n += v[i]*v[i]; }
#pragma unroll
    for (int off = 16; off; off >>= 1) n += __shfl_xor_sync(0xffffffffu, n, off);
    float inv = 1.0f / (sqrtf(n) + 1e-6f);
#pragma unroll
    for (int i = 0; i < 4; i++) {
        int e = base + lane + 32*i;
        float kv = v[i]*inv;
        g_khat[e] = kv;
        __nv_bfloat16 hv = __float2bfloat16(kv);
        g_khh[e] = hv;
        g_khl[e] = __float2bfloat16(kv - __bfloat162float(hv));
    }
}

// ---------------- slot init ----------------
__global__ __launch_bounds__(256)
void init_slots_kernel(const float* __restrict__ Sinit)
{
    int warp = threadIdx.x >> 5, lane = threadIdx.x & 31;
    int wid = blockIdx.x * 8 + warp;
    int bh = wid >> 9;
    int s  = wid & 511;
    int h  = bh & 7;
    const float* src = Sinit + s*DD + h*DH;
    float v[4]; float n = 0.f;
#pragma unroll
    for (int i = 0; i < 4; i++) { v[i] = src[lane + 32*i]; n += v[i]*v[i]; }
#pragma unroll
    for (int off = 16; off; off >>= 1) n += __shfl_xor_sync(0xffffffffu, n, off);
    float inv = 1.0f / (sqrtf(n) + 1e-6f);
    int rb = (bh*KS + s)*DH;
#pragma unroll
    for (int i = 0; i < 4; i++) {
        int e = lane + 32*i;
        float kk = v[i]*inv;
        g_slotk[rb + e] = kk;
        g_slotv[rb + e] = v[i];
        __nv_bfloat16 hv = __float2bfloat16(kk);
        g_skh[rb + e] = hv;
        g_skl[rb + e] = __float2bfloat16(kk - __bfloat162float(hv));
    }
}

// ---------------- dual top-16 + softmax (two independent rows) ----------
__device__ __forceinline__
void topk16_dual(const float* __restrict__ r0p, const float* __restrict__ r1p,
                 int lane, int* oi0, float* op0, int* oi1, float* op1)
{
    float v0[16], v1[16];
#pragma unroll
    for (int i = 0; i < 16; i++) { v0[i] = r0p[i*32 + lane]; v1[i] = r1p[i*32 + lane]; }
    float m0 = 0.f, s0 = 0.f, m1 = 0.f, s1 = 0.f;
#pragma unroll
    for (int it = 0; it < 16; it++) {
        float bv0 = -INFINITY, bv1 = -INFINITY; int bl0 = 0, bl1 = 0;
#pragma unroll
        for (int i = 0; i < 16; i++) {
            if (v0[i] > bv0) { bv0 = v0[i]; bl0 = i; }
            if (v1[i] > bv1) { bv1 = v1[i]; bl1 = i; }
        }
        int bi0 = bl0*32 + lane, bi1 = bl1*32 + lane;
#pragma unroll
        for (int off = 16; off; off >>= 1) {
            float ov0 = __shfl_xor_sync(0xffffffffu, bv0, off);
            int   oj0 = __shfl_xor_sync(0xffffffffu, bi0, off);
            float ov1 = __shfl_xor_sync(0xffffffffu, bv1, off);
            int   oj1 = __shfl_xor_sync(0xffffffffu, bi1, off);
            if (ov0 > bv0 || (ov0 == bv0 && oj0 < bi0)) { bv0 = ov0; bi0 = oj0; }
            if (ov1 > bv1 || (ov1 == bv1 && oj1 < bi1)) { bv1 = ov1; bi1 = oj1; }
        }
        if (it == 0) { m0 = bv0; m1 = bv1; }
        op0[it] = __expf(bv0 - m0); s0 += op0[it]; oi0[it] = bi0;
        op1[it] = __expf(bv1 - m1); s1 += op1[it]; oi1[it] = bi1;
        int wl0 = bi0 & 31, wc0 = bi0 >> 5;
        int wl1 = bi1 & 31, wc1 = bi1 >> 5;
#pragma unroll
        for (int i = 0; i < 16; i++) {
            if (lane == wl0 && i == wc0) v0[i] = -INFINITY;
            if (lane == wl1 && i == wc1) v1[i] = -INFINITY;
        }
    }
    float i0 = 1.0f / s0, i1 = 1.0f / s1;
#pragma unroll
    for (int it = 0; it < 16; it++) { op0[it] *= i0; op1[it] *= i1; }
}

// ---------------- fused chunk kernel: pipelined MMA scores + topk -------
// grid (8, BH), block 512.  32 rows (16 q + 16 khat) x 512 slots, K=128.
// B tiles of 64 slots, cp.async double-buffered.
#define AP 136
#define SP 520
#define CQK_SMEM (32*AP*2*2 + 2*64*AP*2*2 + 32*SP*4)
__global__ __launch_bounds__(512)
void chunk_qk_kernel(int chunk, const float* __restrict__ temp_ptr)
{
    extern __shared__ char smemraw[];
    __nv_bfloat16* Ah = (__nv_bfloat16*)smemraw;       // [32][AP]
    __nv_bfloat16* Al = Ah + 32*AP;
    __nv_bfloat16* Bbase = Al + 32*AP;                 // 2 stages x (Bh|Bl)[64][AP]
    float* scores = (float*)(Bbase + 2*2*64*AP);       // [32][SP]

    int qt = blockIdx.x, bh = blockIdx.y;
    int q0 = qt * 16;
    int tid = threadIdx.x;
    int warp = tid >> 5, lane = tid & 31;
    int wm = warp >> 3, wn = warp & 7;
    int lr = lane >> 2, lc = lane & 3;

    float fq = SCALE_C / temp_ptr[0];
    int tokrow0 = bh*TT + chunk*CH + q0;
    int slotbase = bh*KS;

    // A panel via cp.async (pre-split q / khat)
    {
        int i = tid;            // 32*16 = 512 exactly
        int r = i >> 4, seg = (i & 15)*8;
        int gi = (tokrow0 + (r & 15))*DH + seg;
        const __nv_bfloat16* sh = (r < 16 ? g_qh : g_khh) + gi;
        const __nv_bfloat16* sl = (r < 16 ? g_ql : g_khl) + gi;
        cpa16(&Ah[r*AP + seg], sh);
        cpa16(&Al[r*AP + seg], sl);
    }
    // B tile 0
    {
        __nv_bfloat16* Bh = Bbase;
        __nv_bfloat16* Bl = Bbase + 64*AP;
#pragma unroll
        for (int i = tid; i < 64*16; i += 512) {
            int row = i >> 4, seg = (i & 15)*8;
            int gi = (slotbase + row)*DH + seg;
            cpa16(&Bh[row*AP + seg], &g_skh[gi]);
            cpa16(&Bl[row*AP + seg], &g_skl[gi]);
        }
    }
    CP_COMMIT;

#pragma unroll 1
    for (int t = 0; t < 8; t++) {
        if (t < 7) {
            __nv_bfloat16* Bh = Bbase + ((t+1)&1)*2*64*AP;
            __nv_bfloat16* Bl = Bh + 64*AP;
#pragma unroll
            for (int i = tid; i < 64*16; i += 512) {
                int row = i >> 4, seg = (i & 15)*8;
                int gi = (slotbase + (t+1)*64 + row)*DH + seg;
                cpa16(&Bh[row*AP + seg], &g_skh[gi]);
                cpa16(&Bl[row*AP + seg], &g_skl[gi]);
            }
            CP_COMMIT;
            CP_WAIT(1);
        } else {
            CP_WAIT(0);
        }
        __syncthreads();

        __nv_bfloat16* Bh = Bbase + (t&1)*2*64*AP;
        __nv_bfloat16* Bl = Bh + 64*AP;

        float acc[4] = {0.f, 0.f, 0.f, 0.f};
        int nr = wn*8 + lr;
#pragma unroll
        for (int kt = 0; kt < 8; kt++) {
            int k0 = kt*16;
            unsigned Afh[4], Afl[4];
            int r = wm*16 + lr;
            Afh[0] = *(const unsigned*)&Ah[r*AP + k0 + lc*2];
            Afh[1] = *(const unsigned*)&Ah[(r+8)*AP + k0 + lc*2];
            Afh[2] = *(const unsigned*)&Ah[r*AP + k0 + lc*2 + 8];
            Afh[3] = *(const unsigned*)&Ah[(r+8)*AP + k0 + lc*2 + 8];
            Afl[0] = *(const unsigned*)&Al[r*AP + k0 + lc*2];
            Afl[1] = *(const unsigned*)&Al[(r+8)*AP + k0 + lc*2];
            Afl[2] = *(const unsigned*)&Al[r*AP + k0 + lc*2 + 8];
            Afl[3] = *(const unsigned*)&Al[(r+8)*AP + k0 + lc*2 + 8];
            unsigned Bf0[2], Bf1[2];
            Bf0[0] = *(const unsigned*)&Bh[nr*AP + k0 + lc*2];
            Bf0[1] = *(const unsigned*)&Bh[nr*AP + k0 + lc*2 + 8];
            Bf1[0] = *(const unsigned*)&Bl[nr*AP + k0 + lc*2];
            Bf1[1] = *(const unsigned*)&Bl[nr*AP + k0 + lc*2 + 8];
            mma16816(acc, Afh, Bf0);
            mma16816(acc, Afh, Bf1);
            mma16816(acc, Afl, Bf0);
        }
        float factor = (wm == 0) ? fq : 1.0f;
        int col = t*64 + wn*8 + lc*2;
        int row0 = wm*16 + lr;
        *(float2*)&scores[row0*SP + col]     = make_float2(acc[0]*factor, acc[1]*factor);
        *(float2*)&scores[(row0+8)*SP + col] = make_float2(acc[2]*factor, acc[3]*factor);
        __syncthreads();
    }

    // topk + read / proj. warps 0-7: q rows (2 each); 8-15: khat rows.
    bool isq = warp < 8;
    int qi0 = (warp & 7)*2, qi1 = qi0 + 1;
    int sr0 = isq ? qi0 : (16 + qi0);
    int oi0[16], oi1[16]; float op0[16], op1[16];
    topk16_dual(&scores[sr0*SP], &scores[(sr0+1)*SP], lane, oi0, op0, oi1, op1);

    int tb0 = (tokrow0 + qi0)*DH, tb1 = (tokrow0 + qi1)*DH;

    if (isq) {
        float4 a0 = make_float4(0.f,0.f,0.f,0.f);
        float4 a1 = a0;
#pragma unroll
        for (int k = 0; k < 16; k++) {
            float4 v0 = *(const float4*)&g_slotv[(slotbase + oi0[k])*DH + lane*4];
            float4 v1 = *(const float4*)&g_slotv[(slotbase + oi1[k])*DH + lane*4];
            a0.x += op0[k]*v0.x; a0.y += op0[k]*v0.y; a0.z += op0[k]*v0.z; a0.w += op0[k]*v0.w;
            a1.x += op1[k]*v1.x; a1.y += op1[k]*v1.y; a1.z += op1[k]*v1.z; a1.w += op1[k]*v1.w;
        }
        *(float4*)&g_reads[tb0 + lane*4] = a0;
        *(float4*)&g_reads[tb1 + lane*4] = a1;
    } else {
        float4 w0 = *(const float4*)&g_v[tb0 + lane*4];
        float4 w1 = *(const float4*)&g_v[tb1 + lane*4];
        int eb0 = (bh*CH + q0 + qi0)*KRR;
        int eb1 = (bh*CH + q0 + qi1)*KRR;
#pragma unroll
        for (int k = 0; k < 16; k++) {
            float4 k0 = *(const float4*)&g_slotk[(slotbase + oi0[k])*DH + lane*4];
            float4 k1 = *(const float4*)&g_slotk[(slotbase + oi1[k])*DH + lane*4];
            float d0 = w0.x*k0.x + w0.y*k0.y + w0.z*k0.z + w0.w*k0.w;
            float d1 = w1.x*k1.x + w1.y*k1.y + w1.z*k1.z + w1.w*k1.w;
#pragma unroll
            for (int off = 16; off; off >>= 1) {
                d0 += __shfl_xor_sync(0xffffffffu, d0, off);
                d1 += __shfl_xor_sync(0xffffffffu, d1, off);
            }
            if (lane == 0) {
                g_eidx[eb0 + k] = oi0[k]; g_ewp[eb0 + k] = op0[k]; g_eproj[eb0 + k] = d0;
                g_eidx[eb1 + k] = oi1[k]; g_ewp[eb1 + k] = op1[k]; g_eproj[eb1 + k] = d1;
            }
        }
    }
}

// ---------------- deterministic slot update (writes fp32 + bf16) --------
__global__ __launch_bounds__(256)
void chunk_update_kernel(int chunk)
{
    int bh = blockIdx.y;
    int tid = threadIdx.x;
    int warp = tid >> 5, lane = tid & 31;
    int s = blockIdx.x * 8 + warp;

    __shared__ int   sidx[CH*KRR];
    __shared__ float swp [CH*KRR];
    __shared__ float sprj[CH*KRR];
    int ebase = bh*CH*KRR;
    for (int j = tid; j < CH*KRR; j += 256) {
        sidx[j] = g_eidx[ebase + j];
        swp[j]  = g_ewp[ebase + j];
        sprj[j] = g_eproj[ebase + j];
    }
    __syncthreads();

    int tokbase = (bh*TT + chunk*CH)*DH;

    float accv[4] = {0,0,0,0};
    float acck[4] = {0,0,0,0};
    float swpsum = 0.f, swpp = 0.f;
    for (int b0 = 0; b0 < CH*KRR; b0 += 32) {
        bool mt = (sidx[b0 + lane] == s);
        unsigned bal = __ballot_sync(0xffffffffu, mt);
        while (bal) {
            int jj = b0 + (__ffs(bal) - 1);
            bal &= bal - 1;
            float wp = swp[jj];
            float pj = sprj[jj];
            int cc = jj >> 4;
            const float* vr = g_v    + tokbase + cc*DH;
            const float* kr = g_khat + tokbase + cc*DH;
#pragma unroll
            for (int i = 0; i < 4; i++) {
                int e = lane + 32*i;
                accv[i] += wp * vr[e];
                acck[i] += wp * kr[e];
            }
            swpsum += wp;
            swpp   += wp * pj;
        }
    }
    int rb = (bh*KS + s)*DH;
    float* kd = g_slotk + rb;
    float* vd = g_slotv + rb;
    float nk[4]; float nsum = 0.f;
#pragma unroll
    for (int i = 0; i < 4; i++) {
        int e = lane + 32*i;
        float ok = kd[e];
        float nv = (1.0f - FORGET_C) * vd[e] + ETA_C * (accv[i] - swpp * ok);
        vd[e] = nv;
        nk[i] = ok + ETA_C * (acck[i] - swpsum * ok);
        nsum += nk[i]*nk[i];
    }
#pragma unroll
    for (int off = 16; off; off >>= 1) nsum += __shfl_xor_sync(0xffffffffu, nsum, off);
    float inv = 1.0f / (sqrtf(nsum) + 1e-6f);
#pragma unroll
    for (int i = 0; i < 4; i++) {
        int e = lane + 32*i;
        float val = nk[i]*inv;
        kd[e] = val;
        __nv_bfloat16 hv = __float2bfloat16(val);
        g_skh[rb + e] = hv;
        g_skl[rb + e] = __float2bfloat16(val - __bfloat162float(hv));
    }
}

// ---------------- local sliding-window attention (tensor cores) --------
#define LKP 136
#define LSMEM (4*64*LKP*2)
__global__ __launch_bounds__(128)
void local_mma_kernel()
{
    extern __shared__ __nv_bfloat16 lsm[];
    __nv_bfloat16* Ksh = lsm;              // [64][LKP]
    __nv_bfloat16* Ksl = Ksh + 64*LKP;
    __nv_bfloat16* Vsh = Ksl + 64*LKP;     // [64][LKP]
    __nv_bfloat16* Vsl = Vsh + 64*LKP;
    __nv_bfloat16* Qh = Ksh;               // Q staged transiently in K region
    __nv_bfloat16* Ql = Ksl;

    int q0 = blockIdx.x * 64, bh = blockIdx.y;
    int tid = threadIdx.x, warp = tid >> 5, lane = tid & 31;

    // stage Q (pre-split) via plain vector copies
    for (int i = tid; i < 64*16; i += 128) {
        int r = i >> 4, seg = (i & 15)*8;
        int gi = (bh*TT + q0 + r)*DH + seg;
        *(uint4*)&Qh[r*LKP + seg] = *(const uint4*)&g_qh[gi];
        *(uint4*)&Ql[r*LKP + seg] = *(const uint4*)&g_ql[gi];
    }
    __syncthreads();

    unsigned aqh[8][4], aql[8][4];
    int r0 = warp*16 + (lane >> 2);
#pragma unroll
    for (int kf = 0; kf < 8; kf++) {
        int c = kf*16 + (lane & 3)*2;
        aqh[kf][0] = *(const unsigned*)&Qh[r0*LKP + c];
        aqh[kf][1] = *(const unsigned*)&Qh[(r0+8)*LKP + c];
        aqh[kf][2] = *(const unsigned*)&Qh[r0*LKP + c + 8];
        aqh[kf][3] = *(const unsigned*)&Qh[(r0+8)*LKP + c + 8];
        aql[kf][0] = *(const unsigned*)&Ql[r0*LKP + c];
        aql[kf][1] = *(const unsigned*)&Ql[(r0+8)*LKP + c];
        aql[kf][2] = *(const unsigned*)&Ql[r0*LKP + c + 8];
        aql[kf][3] = *(const unsigned*)&Ql[(r0+8)*LKP + c + 8];
    }

    float m0 = -1e30f, l0 = 0.f, m1 = -1e30f, l1 = 0.f;
    float o[16][4];
#pragma unroll
    for (int i = 0; i < 16; i++)
#pragma unroll
        for (int r = 0; r < 4; r++) o[i][r] = 0.f;

    int qg0 = q0 + warp*16 + (lane >> 2);
    int qg1 = qg0 + 8;
    int kstart = q0 - 512; if (kstart < 0) kstart = 0;

    unsigned vbh = (unsigned)__cvta_generic_to_shared(Vsh);
    unsigned vbl = (unsigned)__cvta_generic_to_shared(Vsl);

#pragma unroll 1
    for (int kt = kstart; kt <= q0; kt += 64) {
        __syncthreads();
        for (int i = tid; i < 64*16; i += 128) {
            int r = i >> 4, seg = (i & 15)*8;
            int gi = (bh*TT + kt + r)*DH + seg;
            cpa16(&Ksh[r*LKP + seg], &g_kh[gi]);
            cpa16(&Ksl[r*LKP + seg], &g_kl[gi]);
            cpa16(&Vsh[r*LKP + seg], &g_vh[gi]);
            cpa16(&Vsl[r*LKP + seg], &g_vl[gi]);
        }
        CP_COMMIT;
        CP_WAIT(0);
        __syncthreads();

        float s[8][4];
#pragma unroll
        for (int n = 0; n < 8; n++)
#pragma unroll
            for (int r = 0; r < 4; r++) s[n][r] = 0.f;
#pragma unroll
        for (int kf = 0; kf < 8; kf++) {
            int c = kf*16 + (lane & 3)*2;
#pragma unroll
            for (int nf = 0; nf < 8; nf++) {
                int key = nf*8 + (lane >> 2);
                unsigned b0[2], b1[2];
                b0[0] = *(const unsigned*)&Ksh[key*LKP + c];
                b0[1] = *(const unsigned*)&Ksh[key*LKP + c + 8];
                b1[0] = *(const unsigned*)&Ksl[key*LKP + c];
                b1[1] = *(const unsigned*)&Ksl[key*LKP + c + 8];
                mma16816(s[nf], aqh[kf], b0);
                mma16816(s[nf], aqh[kf], b1);
                mma16816(s[nf], aql[kf], b0);
            }
        }

        float rm0 = -1e30f, rm1 = -1e30f;
#pragma unroll
        for (int nf = 0; nf < 8; nf++) {
            int kgb = kt + nf*8 + (lane & 3)*2;
#pragma unroll
            for (int e = 0; e < 4; e++) {
                int kg = kgb + (e & 1);
                int qg = (e < 2) ? qg0 : qg1;
                float sv = s[nf][e] * SCALE_C;
                bool ok = (kg <= qg) && (kg > qg - 512);
                sv = ok ? sv : -1e30f;
                s[nf][e] = sv;
                if (e < 2) rm0 = fmaxf(rm0, sv); else rm1 = fmaxf(rm1, sv);
            }
        }
        rm0 = fmaxf(rm0, __shfl_xor_sync(0xffffffffu, rm0, 1));
        rm0 = fmaxf(rm0, __shfl_xor_sync(0xffffffffu, rm0, 2));
        rm1 = fmaxf(rm1, __shfl_xor_sync(0xffffffffu, rm1, 1));
        rm1 = fmaxf(rm1, __shfl_xor_sync(0xffffffffu, rm1, 2));
        float mn0 = fmaxf(m0, rm0), mn1 = fmaxf(m1, rm1);
        float c0 = __expf(m0 - mn0), c1 = __expf(m1 - mn1);
        m0 = mn0; m1 = mn1;

        float ps0 = 0.f, ps1 = 0.f;
#pragma unroll
        for (int nf = 0; nf < 8; nf++)
#pragma unroll
            for (int e = 0; e < 4; e++) {
                float sv = s[nf][e];
                float p = __expf(sv - ((e < 2) ? mn0 : mn1));
                p = (sv > -1e29f) ? p : 0.f;
                s[nf][e] = p;
                if (e < 2) ps0 += p; else ps1 += p;
            }
        ps0 += __shfl_xor_sync(0xffffffffu, ps0, 1);
        ps0 += __shfl_xor_sync(0xffffffffu, ps0, 2);
        ps1 += __shfl_xor_sync(0xffffffffu, ps1, 1);
        ps1 += __shfl_xor_sync(0xffffffffu, ps1, 2);
        l0 = l0*c0 + ps0;
        l1 = l1*c1 + ps1;

#pragma unroll
        for (int n = 0; n < 16; n++) {
            o[n][0] *= c0; o[n][1] *= c0; o[n][2] *= c1; o[n][3] *= c1;
        }

        unsigned ph[4][4], pl[4][4];
#pragma unroll
        for (int kf2 = 0; kf2 < 4; kf2++) {
            pack_hl(s[2*kf2][0],   s[2*kf2][1],   ph[kf2][0], pl[kf2][0]);
            pack_hl(s[2*kf2][2],   s[2*kf2][3],   ph[kf2][1], pl[kf2][1]);
            pack_hl(s[2*kf2+1][0], s[2*kf2+1][1], ph[kf2][2], pl[kf2][2]);
            pack_hl(s[2*kf2+1][2], s[2*kf2+1][3], ph[kf2][3], pl[kf2][3]);
        }

#pragma unroll
        for (int nf2 = 0; nf2 < 16; nf2++) {
#pragma unroll
            for (int kf2 = 0; kf2 < 4; kf2++) {
                unsigned off = ((unsigned)((kf2*16 + (lane & 15))*LKP + nf2*8)) * 2u;
                unsigned bv[2], bw[2];
                asm volatile(
                    "ldmatrix.sync.aligned.m8n8.x2.trans.shared.b16 {%0,%1}, [%2];"
                    : "=r"(bv[0]), "=r"(bv[1]) : "r"(vbh + off));
                asm volatile(
                    "ldmatrix.sync.aligned.m8n8.x2.trans.shared.b16 {%0,%1}, [%2];"
                    : "=r"(bw[0]), "=r"(bw[1]) : "r"(vbl + off));
                mma16816(o[nf2], ph[kf2], bv);
                mma16816(o[nf2], pl[kf2], bv);
                mma16816(o[nf2], ph[kf2], bw);
            }
        }
    }

    float iv0 = 1.0f / l0, iv1 = 1.0f / l1;
    float* out0 = g_local + (bh*TT + qg0)*DH;
    float* out1 = g_local + (bh*TT + qg1)*DH;
#pragma unroll
    for (int n = 0; n < 16; n++) {
        int col = n*8 + (lane & 3)*2;
        *(float2*)(out0 + col) = make_float2(o[n][0]*iv0, o[n][1]*iv0);
        *(float2*)(out1 + col) = make_float2(o[n][2]*iv1, o[n][3]*iv1);
    }
}

// ---------------- launch ----------------
extern "C" void kernel_launch(void* const* d_in, const int* in_sizes, int n_in,
                              void* d_out, int out_size)
{
    const float* x     = (const float*)d_in[0];
    const float* Wqkv  = (const float*)d_in[1];
    const float* bqkv  = (const float*)d_in[2];
    const float* Wo    = (const float*)d_in[3];
    const float* bo    = (const float*)d_in[4];
    const float* Sinit = (const float*)d_in[5];
    const float* temp  = (const float*)d_in[6];
    float* out = (float*)d_out;

    cudaFuncSetAttribute(chunk_qk_kernel,
                         cudaFuncAttributeMaxDynamicSharedMemorySize, CQK_SMEM);
    cudaFuncSetAttribute(local_mma_kernel,
                         cudaFuncAttributeMaxDynamicSharedMemorySize, LSMEM);

    init_slots_kernel<<<BH*KS/8, 256>>>(Sinit);

    mma_gemm<<<dim3(3072/128, (BB*TT)/128), 256>>>(x, Wqkv, bqkv, nullptr, DD, 0, 3072);
    khat_kernel<<<BHT/8, 256>>>();

    for (int ch = 0; ch < NCH; ch++) {
        chunk_qk_kernel<<<dim3(8, BH), 512, CQK_SMEM>>>(ch, temp);
        chunk_update_kernel<<<dim3(64, BH), 256>>>(ch);
    }

    local_mma_kernel<<<dim3(TT/64, BH), 128, LSMEM>>>();

    mma_gemm<<<dim3(DD/128, (BB*TT)/128), 256>>>(nullptr, Wo, bo, out, DD, 1, DD);

    (void)in_sizes; (void)n_in; (void)out_size;
}